// round 2
// baseline (speedup 1.0000x reference)
#include <cuda_runtime.h>
#include <cuda_bf16.h>
#include <math.h>

// Problem dims (fixed by reference)
#define T_SEQ   1536
#define D_MODEL 2880
#define NH      64
#define NKV     8
#define HD      64
#define QKV_DIM 5120          // 64*(64+16)
#define QDIM    4096          // NH*HD
#define WIN     128
#define SM_SCALE 0.125f

// Scratch (allocation-free rule: device globals)
__device__ float g_qkv[T_SEQ * QKV_DIM];   // 31.4 MB
__device__ float g_attn[T_SEQ * QDIM];     // 25.2 MB

// ---------------------------------------------------------------------------
// SGEMM: C[M,N] = A[M,K] @ B[K,N] + bias[N]
// 128x128 block tile, BK=8, 256 threads, 8x8 per-thread microtile.
// M, K multiples of 8/128 guaranteed here; only N needs guarding (2880).
// ---------------------------------------------------------------------------
#define BM 128
#define BN 128
#define BK 8

__global__ void __launch_bounds__(256) sgemm_bias_kernel(
    const float* __restrict__ A, const float* __restrict__ B,
    const float* __restrict__ bias, float* __restrict__ C,
    int M, int N, int K)
{
    __shared__ float As[BK][BM];
    __shared__ float Bs[BK][BN];

    const int tid = threadIdx.x;
    const int m0 = blockIdx.y * BM;
    const int n0 = blockIdx.x * BN;
    const int tx = tid & 15;          // 0..15 -> 8 cols each
    const int ty = tid >> 4;          // 0..15 -> 8 rows each

    // A tile load mapping: one float4 along K per thread
    const int a_row = tid >> 1;           // 0..127
    const int a_k   = (tid & 1) * 4;      // 0 or 4
    // B tile load mapping: one float4 along N per thread
    const int b_row = tid >> 5;           // 0..7
    const int b_col = (tid & 31) * 4;     // 0..124

    const bool bvalid = (n0 + b_col) < N;

    const float* Aptr = A + (size_t)(m0 + a_row) * K + a_k;
    const float* Bptr = B + (size_t)b_row * N + n0 + b_col;

    float acc[8][8];
    #pragma unroll
    for (int i = 0; i < 8; i++)
        #pragma unroll
        for (int j = 0; j < 8; j++) acc[i][j] = 0.f;

    for (int k0 = 0; k0 < K; k0 += BK) {
        float4 av = *(const float4*)(Aptr + k0);
        As[a_k + 0][a_row] = av.x;
        As[a_k + 1][a_row] = av.y;
        As[a_k + 2][a_row] = av.z;
        As[a_k + 3][a_row] = av.w;
        float4 bv = bvalid ? *(const float4*)(Bptr + (size_t)k0 * N)
                           : make_float4(0.f, 0.f, 0.f, 0.f);
        *(float4*)&Bs[b_row][b_col] = bv;
        __syncthreads();

        #pragma unroll
        for (int k = 0; k < BK; k++) {
            float a[8], b[8];
            *(float4*)&a[0] = *(const float4*)&As[k][ty * 8];
            *(float4*)&a[4] = *(const float4*)&As[k][ty * 8 + 4];
            *(float4*)&b[0] = *(const float4*)&Bs[k][tx * 8];
            *(float4*)&b[4] = *(const float4*)&Bs[k][tx * 8 + 4];
            #pragma unroll
            for (int i = 0; i < 8; i++)
                #pragma unroll
                for (int j = 0; j < 8; j++)
                    acc[i][j] = fmaf(a[i], b[j], acc[i][j]);
        }
        __syncthreads();
    }

    #pragma unroll
    for (int i = 0; i < 8; i++) {
        int row = m0 + ty * 8 + i;
        #pragma unroll
        for (int j = 0; j < 8; j += 4) {
            int col = n0 + tx * 8 + j;
            if (col < N) {
                float4 bb = *(const float4*)&bias[col];
                float4 o;
                o.x = acc[i][j + 0] + bb.x;
                o.y = acc[i][j + 1] + bb.y;
                o.z = acc[i][j + 2] + bb.z;
                o.w = acc[i][j + 3] + bb.w;
                *(float4*)&C[(size_t)row * N + col] = o;
            }
        }
    }
}

// ---------------------------------------------------------------------------
// RoPE (YaRN / NTK-by-parts, gpt-oss params) applied in-place to q and k
// slices of the qkv buffer. One (t, head) pair per (blockIdx.x, warp row).
// ---------------------------------------------------------------------------
__global__ void rope_kernel(float* __restrict__ qkv)
{
    const int t  = blockIdx.x;
    const int hh = blockIdx.y * blockDim.y + threadIdx.y;   // 0..71
    if (hh >= NH + NKV) return;
    const int i = threadIdx.x;                               // 0..31

    // inv_freq in double, rounded to fp32 (matches numpy fp32 tables closely)
    const double lgbase = log(150000.0);
    const double low  = 32.0 * log(1024.0 / (32.0 * 2.0 * M_PI)) / lgbase;
    const double high = 32.0 * log(1024.0 / ( 1.0 * 2.0 * M_PI)) / lgbase;
    double freq = pow(150000.0, (double)(2 * i) / 64.0);
    double ramp = ((double)i - low) / (high - low);
    ramp = fmin(1.0, fmax(0.0, ramp));
    double invf = ramp / (32.0 * freq) + (1.0 - ramp) / freq;

    float ang = (float)t * (float)invf;
    const float conc = 0.1f * logf(32.0f) + 1.0f;
    float s, c;
    sincosf(ang, &s, &c);
    c *= conc; s *= conc;

    float* p = qkv + (size_t)t * QKV_DIM
             + (hh < NH ? hh * HD : QDIM + (hh - NH) * HD);
    float x1 = p[i], x2 = p[i + 32];
    p[i]      = x1 * c - x2 * s;
    p[i + 32] = x2 * c + x1 * s;
}

// ---------------------------------------------------------------------------
// Sliding-window GQA attention with sink logits.
// Block = (token t, kv head). 256 threads = 8 warps = 8 query heads in group.
// K/V window staged in smem with pitch 65 (odd -> conflict-free both ways).
// ---------------------------------------------------------------------------
#define KV_PITCH 65

__global__ void __launch_bounds__(256) attn_kernel(
    const float* __restrict__ qkv, const float* __restrict__ sinks,
    float* __restrict__ attn)
{
    extern __shared__ float sm[];
    float* Ks = sm;                       // WIN * 65
    float* Vs = Ks + WIN * KV_PITCH;      // WIN * 65
    float* qs = Vs + WIN * KV_PITCH;      // 8 * 64
    float* ws = qs + NKV * HD;            // 8 * 128 (note: 8 q-heads * WIN)

    const int t   = blockIdx.x;
    const int hkv = blockIdx.y;
    const int j0  = max(0, t - (WIN - 1));
    const int cnt = t - j0 + 1;
    const int tid = threadIdx.x;

    for (int idx = tid; idx < cnt * HD; idx += 256) {
        int j = idx >> 6, d = idx & 63;
        const float* row = qkv + (size_t)(j0 + j) * QKV_DIM + hkv * HD;
        Ks[j * KV_PITCH + d] = row[QDIM + d];
        Vs[j * KV_PITCH + d] = row[QDIM + NKV * HD + d];
    }
    for (int idx = tid; idx < 8 * HD; idx += 256)
        qs[idx] = qkv[(size_t)t * QKV_DIM + hkv * (8 * HD) + idx];
    __syncthreads();

    const int warp = tid >> 5;   // q head within group (m)
    const int lane = tid & 31;

    float sc[4];
    float mmax = -INFINITY;
    #pragma unroll
    for (int r = 0; r < 4; r++) {
        int j = lane + r * 32;
        if (j < cnt) {
            const float* kr = &Ks[j * KV_PITCH];
            const float* qr = &qs[warp * HD];
            float dot = 0.f;
            #pragma unroll
            for (int d = 0; d < HD; d++) dot = fmaf(qr[d], kr[d], dot);
            sc[r] = dot * SM_SCALE;
            mmax = fmaxf(mmax, sc[r]);
        } else {
            sc[r] = -INFINITY;
        }
    }
    #pragma unroll
    for (int o = 16; o; o >>= 1) mmax = fmaxf(mmax, __shfl_xor_sync(~0u, mmax, o));

    float ssum = 0.f;
    #pragma unroll
    for (int r = 0; r < 4; r++) {
        float e = (sc[r] == -INFINITY) ? 0.f : expf(sc[r] - mmax);
        sc[r] = e;
        ssum += e;
    }
    #pragma unroll
    for (int o = 16; o; o >>= 1) ssum += __shfl_xor_sync(~0u, ssum, o);

    const float denom = ssum + expf(sinks[hkv * 8 + warp] - mmax);
    const float invd = 1.f / denom;

    #pragma unroll
    for (int r = 0; r < 4; r++) {
        int j = lane + r * 32;
        if (j < cnt) ws[warp * WIN + j] = sc[r] * invd;
    }
    __syncwarp();

    #pragma unroll
    for (int d2 = 0; d2 < 2; d2++) {
        int d = lane + d2 * 32;
        float acc = 0.f;
        for (int j = 0; j < cnt; j++)
            acc = fmaf(ws[warp * WIN + j], Vs[j * KV_PITCH + d], acc);
        attn[(size_t)t * QDIM + hkv * (8 * HD) + warp * HD + d] = acc;
    }
}

// ---------------------------------------------------------------------------
extern "C" void kernel_launch(void* const* d_in, const int* in_sizes, int n_in,
                              void* d_out, int out_size)
{
    const float* x      = (const float*)d_in[0];
    const float* W_qkv  = (const float*)d_in[1];
    const float* b_qkv  = (const float*)d_in[2];
    const float* W_out  = (const float*)d_in[3];
    const float* b_out  = (const float*)d_in[4];
    const float* sinks  = (const float*)d_in[5];
    float* out = (float*)d_out;

    float *qkv_ptr, *attn_ptr;
    cudaGetSymbolAddress((void**)&qkv_ptr, g_qkv);
    cudaGetSymbolAddress((void**)&attn_ptr, g_attn);

    const int attn_smem = (WIN * KV_PITCH * 2 + NKV * HD + 8 * WIN) * (int)sizeof(float);
    cudaFuncSetAttribute(attn_kernel, cudaFuncAttributeMaxDynamicSharedMemorySize,
                         attn_smem);

    // 1) qkv = x @ W_qkv + b_qkv          (1536 x 5120, K=2880)
    {
        dim3 grid(QKV_DIM / BN, T_SEQ / BM);
        sgemm_bias_kernel<<<grid, 256>>>(x, W_qkv, b_qkv, qkv_ptr,
                                         T_SEQ, QKV_DIM, D_MODEL);
    }
    // 2) RoPE in place on q,k slices
    {
        dim3 grid(T_SEQ, 9);
        dim3 block(32, 8);
        rope_kernel<<<grid, block>>>(qkv_ptr);
    }
    // 3) sliding-window GQA attention with sinks
    {
        dim3 grid(T_SEQ, NKV);
        attn_kernel<<<grid, 256, attn_smem>>>(qkv_ptr, sinks, attn_ptr);
    }
    // 4) out = attn @ W_out + b_out       (1536 x 2880, K=4096)
    {
        dim3 grid((D_MODEL + BN - 1) / BN, T_SEQ / BM);
        sgemm_bias_kernel<<<grid, 256>>>(attn_ptr, W_out, b_out, out,
                                         T_SEQ, D_MODEL, QDIM);
    }
}

// round 5
// speedup vs baseline: 1.5071x; 1.5071x over previous
#include <cuda_runtime.h>
#include <cuda_bf16.h>
#include <math.h>
#include <cstdint>

// Problem dims (fixed by reference)
#define T_SEQ   1536
#define D_MODEL 2880
#define NH      64
#define NKV     8
#define HD      64
#define QKV_DIM 5120          // 64*(64+16)
#define QDIM    4096          // NH*HD
#define WIN     128
#define SM_SCALE 0.125f

// Scratch (allocation-free rule: device globals)
__device__ float g_qkv[T_SEQ * QKV_DIM];   // 31.4 MB
__device__ float g_attn[T_SEQ * QDIM];     // 25.2 MB

// ===========================================================================
// HMMA (mma.sync) helpers — plain sm_80+ PTX, assembles for .target sm_103
// ===========================================================================
__device__ __forceinline__ uint32_t smem_u32(const void* p) {
    uint32_t a;
    asm("{ .reg .u64 t; cvta.to.shared.u64 t, %1; cvt.u32.u64 %0, t; }"
        : "=r"(a) : "l"(p));
    return a;
}
__device__ __forceinline__ void ldsm_x4(uint32_t r[4], uint32_t a) {
    asm volatile("ldmatrix.sync.aligned.m8n8.x4.shared.b16 {%0,%1,%2,%3}, [%4];"
        : "=r"(r[0]), "=r"(r[1]), "=r"(r[2]), "=r"(r[3]) : "r"(a));
}
__device__ __forceinline__ void ldsm_x2t(uint32_t r[2], uint32_t a) {
    asm volatile("ldmatrix.sync.aligned.m8n8.x2.trans.shared.b16 {%0,%1}, [%2];"
        : "=r"(r[0]), "=r"(r[1]) : "r"(a));
}
__device__ __forceinline__ void mma16816(float c[4], const uint32_t a[4],
                                         const uint32_t b[2]) {
    asm volatile(
        "mma.sync.aligned.m16n8k16.row.col.f32.bf16.bf16.f32 "
        "{%0,%1,%2,%3}, {%4,%5,%6,%7}, {%8,%9}, {%0,%1,%2,%3};"
        : "+f"(c[0]), "+f"(c[1]), "+f"(c[2]), "+f"(c[3])
        : "r"(a[0]), "r"(a[1]), "r"(a[2]), "r"(a[3]), "r"(b[0]), "r"(b[1]));
}
// split fp32 pair into (hi, lo) packed bf16x2
__device__ __forceinline__ void split_pair(float x, float y,
                                           uint32_t& hi, uint32_t& lo) {
    __nv_bfloat16 hx = __float2bfloat16(x);
    __nv_bfloat16 hy = __float2bfloat16(y);
    float rx = x - __bfloat162float(hx);
    float ry = y - __bfloat162float(hy);
    __nv_bfloat162 hp = __halves2bfloat162(hx, hy);
    __nv_bfloat162 lp = __floats2bfloat162_rn(rx, ry);
    hi = *reinterpret_cast<uint32_t*>(&hp);
    lo = *reinterpret_cast<uint32_t*>(&lp);
}

// ===========================================================================
// Split-bf16 HMMA GEMM with bias: C[M,N] = A[M,K] @ B[K,N] + bias[N]
//   CTA 128x128, BK=32, 8 warps (2m x 4n), warp tile 64x32.
//   A smem [m][k] pitch 40 bf16 (80 B); B smem [k][n] pitch 136 bf16 (272 B).
//   A*B ~= Ahi*Bhi + Alo*Bhi + Ahi*Blo, fp32 accumulators.
// Requirements: M % 128 == 0, K % 32 == 0; N guarded (float4 granularity).
// ===========================================================================
#define SA_HI_OFF 0
#define SA_LO_OFF 10240
#define SB_HI_OFF 20480
#define SB_LO_OFF 29184
#define EP_PITCH  132
#define GEMM_SMEM_BYTES (128 * EP_PITCH * 4)   // 67584 (> mainloop 37888)

__global__ void __launch_bounds__(256) hmma_gemm_bias(
    const float* __restrict__ A, const float* __restrict__ B,
    const float* __restrict__ bias, float* __restrict__ C,
    int M, int N, int K)
{
    extern __shared__ char smem[];
    const uint32_t sb = smem_u32(smem);
    const int tid = threadIdx.x, lane = tid & 31, wid = tid >> 5;
    const int wm = wid >> 2, wn = wid & 3;
    const int m0 = blockIdx.y * 128, n0 = blockIdx.x * 128;

    float acc[4][4][4];
    #pragma unroll
    for (int mi = 0; mi < 4; mi++)
        #pragma unroll
        for (int ni = 0; ni < 4; ni++)
            #pragma unroll
            for (int q = 0; q < 4; q++) acc[mi][ni][q] = 0.f;

    float4 stA[4], stB[4];
    // prologue: load chunk 0 into registers
    #pragma unroll
    for (int r = 0; r < 4; r++) {
        int i = tid + r * 256;
        int m = i >> 3, kq = (i & 7) * 4;
        stA[r] = *(const float4*)(A + (size_t)(m0 + m) * K + kq);
    }
    #pragma unroll
    for (int r = 0; r < 4; r++) {
        int i = tid + r * 256;
        int k = i >> 5, nq = (i & 31) * 4;
        stB[r] = (n0 + nq < N) ? *(const float4*)(B + (size_t)k * N + n0 + nq)
                               : make_float4(0.f, 0.f, 0.f, 0.f);
    }

    const int nch = K >> 5;
    for (int ch = 0; ch < nch; ch++) {
        __syncthreads();   // prior chunk's ldmatrix reads done before overwrite
        // convert + store stage
        #pragma unroll
        for (int r = 0; r < 4; r++) {
            int i = tid + r * 256;
            int m = i >> 3, kq = (i & 7) * 4;
            uint32_t h0, l0, h1, l1;
            split_pair(stA[r].x, stA[r].y, h0, l0);
            split_pair(stA[r].z, stA[r].w, h1, l1);
            uint32_t off = (uint32_t)m * 80u + (uint32_t)kq * 2u;
            *(uint2*)(smem + SA_HI_OFF + off) = make_uint2(h0, h1);
            *(uint2*)(smem + SA_LO_OFF + off) = make_uint2(l0, l1);
        }
        #pragma unroll
        for (int r = 0; r < 4; r++) {
            int i = tid + r * 256;
            int k = i >> 5, nq = (i & 31) * 4;
            uint32_t h0, l0, h1, l1;
            split_pair(stB[r].x, stB[r].y, h0, l0);
            split_pair(stB[r].z, stB[r].w, h1, l1);
            uint32_t off = (uint32_t)k * 272u + (uint32_t)nq * 2u;
            *(uint2*)(smem + SB_HI_OFF + off) = make_uint2(h0, h1);
            *(uint2*)(smem + SB_LO_OFF + off) = make_uint2(l0, l1);
        }
        __syncthreads();

        // prefetch next chunk (LDG latency hides under MMA below)
        if (ch + 1 < nch) {
            const int k0n = (ch + 1) * 32;
            #pragma unroll
            for (int r = 0; r < 4; r++) {
                int i = tid + r * 256;
                int m = i >> 3, kq = (i & 7) * 4;
                stA[r] = *(const float4*)(A + (size_t)(m0 + m) * K + k0n + kq);
            }
            #pragma unroll
            for (int r = 0; r < 4; r++) {
                int i = tid + r * 256;
                int k = i >> 5, nq = (i & 31) * 4;
                stB[r] = (n0 + nq < N)
                    ? *(const float4*)(B + (size_t)(k0n + k) * N + n0 + nq)
                    : make_float4(0.f, 0.f, 0.f, 0.f);
            }
        }

        // MMA over two k16 steps
        #pragma unroll
        for (int s = 0; s < 2; s++) {
            uint32_t ah[4][4], al[4][4], bh[4][2], bl[4][2];
            const uint32_t arow  = (uint32_t)(lane & 15);
            const uint32_t acolb = (uint32_t)(s * 32 + (lane >> 4) * 16);
            #pragma unroll
            for (int mi = 0; mi < 4; mi++) {
                uint32_t addr = sb + SA_HI_OFF
                              + (uint32_t)(wm * 64 + mi * 16 + arow) * 80u + acolb;
                ldsm_x4(ah[mi], addr);
                ldsm_x4(al[mi], addr + (SA_LO_OFF - SA_HI_OFF));
            }
            const uint32_t brow = (uint32_t)(s * 16 + (lane & 15));
            #pragma unroll
            for (int ni = 0; ni < 4; ni++) {
                uint32_t addr = sb + SB_HI_OFF + brow * 272u
                              + (uint32_t)(wn * 32 + ni * 8) * 2u;
                ldsm_x2t(bh[ni], addr);
                ldsm_x2t(bl[ni], addr + (SB_LO_OFF - SB_HI_OFF));
            }
            #pragma unroll
            for (int mi = 0; mi < 4; mi++)
                #pragma unroll
                for (int ni = 0; ni < 4; ni++) {
                    mma16816(acc[mi][ni], ah[mi], bh[ni]);
                    mma16816(acc[mi][ni], al[mi], bh[ni]);
                    mma16816(acc[mi][ni], ah[mi], bl[ni]);
                }
        }
    }
    __syncthreads();

    // ---- epilogue: regs -> smem (pad 132) -> coalesced float4 STG + bias ----
    float* ep = (float*)smem;
    #pragma unroll
    for (int mi = 0; mi < 4; mi++) {
        int r0 = wm * 64 + mi * 16 + (lane >> 2);
        #pragma unroll
        for (int ni = 0; ni < 4; ni++) {
            int c = wn * 32 + ni * 8 + (lane & 3) * 2;
            ep[r0 * EP_PITCH + c]           = acc[mi][ni][0];
            ep[r0 * EP_PITCH + c + 1]       = acc[mi][ni][1];
            ep[(r0 + 8) * EP_PITCH + c]     = acc[mi][ni][2];
            ep[(r0 + 8) * EP_PITCH + c + 1] = acc[mi][ni][3];
        }
    }
    __syncthreads();
    for (int i = tid; i < 4096; i += 256) {
        int r = i >> 5, cq = (i & 31) * 4;
        int col = n0 + cq;
        if (col < N) {
            float4 b4 = *(const float4*)(bias + col);
            float4 o;
            o.x = ep[r * EP_PITCH + cq + 0] + b4.x;
            o.y = ep[r * EP_PITCH + cq + 1] + b4.y;
            o.z = ep[r * EP_PITCH + cq + 2] + b4.z;
            o.w = ep[r * EP_PITCH + cq + 3] + b4.w;
            *(float4*)(C + (size_t)(m0 + r) * N + col) = o;
        }
    }
}

// ---------------------------------------------------------------------------
// RoPE (YaRN / NTK-by-parts, gpt-oss params) applied in-place to q and k.
// ---------------------------------------------------------------------------
__global__ void rope_kernel(float* __restrict__ qkv)
{
    const int t  = blockIdx.x;
    const int hh = blockIdx.y * blockDim.y + threadIdx.y;   // 0..71
    if (hh >= NH + NKV) return;
    const int i = threadIdx.x;                               // 0..31

    const double lgbase = log(150000.0);
    const double low  = 32.0 * log(1024.0 / (32.0 * 2.0 * M_PI)) / lgbase;
    const double high = 32.0 * log(1024.0 / ( 1.0 * 2.0 * M_PI)) / lgbase;
    double freq = pow(150000.0, (double)(2 * i) / 64.0);
    double ramp = ((double)i - low) / (high - low);
    ramp = fmin(1.0, fmax(0.0, ramp));
    double invf = ramp / (32.0 * freq) + (1.0 - ramp) / freq;

    float ang = (float)t * (float)invf;
    const float conc = 0.1f * logf(32.0f) + 1.0f;
    float s, c;
    sincosf(ang, &s, &c);
    c *= conc; s *= conc;

    float* p = qkv + (size_t)t * QKV_DIM
             + (hh < NH ? hh * HD : QDIM + (hh - NH) * HD);
    float x1 = p[i], x2 = p[i + 32];
    p[i]      = x1 * c - x2 * s;
    p[i + 32] = x2 * c + x1 * s;
}

// ---------------------------------------------------------------------------
// Sliding-window GQA attention with sink logits.
// ---------------------------------------------------------------------------
#define KV_PITCH 65

__global__ void __launch_bounds__(256) attn_kernel(
    const float* __restrict__ qkv, const float* __restrict__ sinks,
    float* __restrict__ attn)
{
    extern __shared__ float sm[];
    float* Ks = sm;                       // WIN * 65
    float* Vs = Ks + WIN * KV_PITCH;      // WIN * 65
    float* qs = Vs + WIN * KV_PITCH;      // 8 * 64
    float* ws = qs + NKV * HD;            // 8 * 128

    const int t   = blockIdx.x;
    const int hkv = blockIdx.y;
    const int j0  = max(0, t - (WIN - 1));
    const int cnt = t - j0 + 1;
    const int tid = threadIdx.x;

    for (int idx = tid; idx < cnt * HD; idx += 256) {
        int j = idx >> 6, d = idx & 63;
        const float* row = qkv + (size_t)(j0 + j) * QKV_DIM + hkv * HD;
        Ks[j * KV_PITCH + d] = row[QDIM + d];
        Vs[j * KV_PITCH + d] = row[QDIM + NKV * HD + d];
    }
    for (int idx = tid; idx < 8 * HD; idx += 256)
        qs[idx] = qkv[(size_t)t * QKV_DIM + hkv * (8 * HD) + idx];
    __syncthreads();

    const int warp = tid >> 5;
    const int lane = tid & 31;

    float sc[4];
    float mmax = -INFINITY;
    #pragma unroll
    for (int r = 0; r < 4; r++) {
        int j = lane + r * 32;
        if (j < cnt) {
            const float* kr = &Ks[j * KV_PITCH];
            const float* qr = &qs[warp * HD];
            float dot = 0.f;
            #pragma unroll
            for (int d = 0; d < HD; d++) dot = fmaf(qr[d], kr[d], dot);
            sc[r] = dot * SM_SCALE;
            mmax = fmaxf(mmax, sc[r]);
        } else {
            sc[r] = -INFINITY;
        }
    }
    #pragma unroll
    for (int o = 16; o; o >>= 1) mmax = fmaxf(mmax, __shfl_xor_sync(~0u, mmax, o));

    float ssum = 0.f;
    #pragma unroll
    for (int r = 0; r < 4; r++) {
        float e = (sc[r] == -INFINITY) ? 0.f : expf(sc[r] - mmax);
        sc[r] = e;
        ssum += e;
    }
    #pragma unroll
    for (int o = 16; o; o >>= 1) ssum += __shfl_xor_sync(~0u, ssum, o);

    const float denom = ssum + expf(sinks[hkv * 8 + warp] - mmax);
    const float invd = 1.f / denom;

    #pragma unroll
    for (int r = 0; r < 4; r++) {
        int j = lane + r * 32;
        if (j < cnt) ws[warp * WIN + j] = sc[r] * invd;
    }
    __syncwarp();

    #pragma unroll
    for (int d2 = 0; d2 < 2; d2++) {
        int d = lane + d2 * 32;
        float acc = 0.f;
        for (int j = 0; j < cnt; j++)
            acc = fmaf(ws[warp * WIN + j], Vs[j * KV_PITCH + d], acc);
        attn[(size_t)t * QDIM + hkv * (8 * HD) + warp * HD + d] = acc;
    }
}

// ---------------------------------------------------------------------------
extern "C" void kernel_launch(void* const* d_in, const int* in_sizes, int n_in,
                              void* d_out, int out_size)
{
    const float* x      = (const float*)d_in[0];
    const float* W_qkv  = (const float*)d_in[1];
    const float* b_qkv  = (const float*)d_in[2];
    const float* W_out  = (const float*)d_in[3];
    const float* b_out  = (const float*)d_in[4];
    const float* sinks  = (const float*)d_in[5];
    float* out = (float*)d_out;

    float *qkv_ptr, *attn_ptr;
    cudaGetSymbolAddress((void**)&qkv_ptr, g_qkv);
    cudaGetSymbolAddress((void**)&attn_ptr, g_attn);

    cudaFuncSetAttribute(hmma_gemm_bias,
                         cudaFuncAttributeMaxDynamicSharedMemorySize,
                         GEMM_SMEM_BYTES);
    const int attn_smem = (WIN * KV_PITCH * 2 + NKV * HD + 8 * WIN) * (int)sizeof(float);
    cudaFuncSetAttribute(attn_kernel, cudaFuncAttributeMaxDynamicSharedMemorySize,
                         attn_smem);

    // 1) qkv = x @ W_qkv + b_qkv          (1536 x 5120, K=2880)
    {
        dim3 grid(QKV_DIM / 128, T_SEQ / 128);
        hmma_gemm_bias<<<grid, 256, GEMM_SMEM_BYTES>>>(
            x, W_qkv, b_qkv, qkv_ptr, T_SEQ, QKV_DIM, D_MODEL);
    }
    // 2) RoPE in place on q,k slices
    {
        dim3 grid(T_SEQ, 9);
        dim3 block(32, 8);
        rope_kernel<<<grid, block>>>(qkv_ptr);
    }
    // 3) sliding-window GQA attention with sinks
    {
        dim3 grid(T_SEQ, NKV);
        attn_kernel<<<grid, 256, attn_smem>>>(qkv_ptr, sinks, attn_ptr);
    }
    // 4) out = attn @ W_out + b_out       (1536 x 2880, K=4096)
    {
        dim3 grid((D_MODEL + 127) / 128, T_SEQ / 128);
        hmma_gemm_bias<<<grid, 256, GEMM_SMEM_BYTES>>>(
            attn_ptr, W_out, b_out, out, T_SEQ, D_MODEL, QDIM);
    }
}

// round 7
// speedup vs baseline: 3.1565x; 2.0943x over previous
#include <cuda_runtime.h>
#include <cuda_bf16.h>
#include <math.h>
#include <cstdint>

// Problem dims (fixed by reference)
#define T_SEQ   1536
#define D_MODEL 2880
#define NH      64
#define NKV     8
#define HD      64
#define QKV_DIM 5120          // 64*(64+16)
#define QDIM    4096          // NH*HD
#define WIN     128
#define SM_SCALE 0.125f

// Scratch (allocation-free rule: device globals)
__device__ float g_qkv[T_SEQ * QKV_DIM];   // 31.4 MB
__device__ float g_attn[T_SEQ * QDIM];     // 25.2 MB
__device__ float g_invf[32];               // rope inv_freq table

// ===========================================================================
// HMMA (mma.sync) helpers — plain sm_80+ PTX, assembles for .target sm_103
// ===========================================================================
__device__ __forceinline__ uint32_t smem_u32(const void* p) {
    uint32_t a;
    asm("{ .reg .u64 t; cvta.to.shared.u64 t, %1; cvt.u32.u64 %0, t; }"
        : "=r"(a) : "l"(p));
    return a;
}
__device__ __forceinline__ void ldsm_x4(uint32_t r[4], uint32_t a) {
    asm volatile("ldmatrix.sync.aligned.m8n8.x4.shared.b16 {%0,%1,%2,%3}, [%4];"
        : "=r"(r[0]), "=r"(r[1]), "=r"(r[2]), "=r"(r[3]) : "r"(a));
}
__device__ __forceinline__ void ldsm_x2t(uint32_t r[2], uint32_t a) {
    asm volatile("ldmatrix.sync.aligned.m8n8.x2.trans.shared.b16 {%0,%1}, [%2];"
        : "=r"(r[0]), "=r"(r[1]) : "r"(a));
}
__device__ __forceinline__ void mma16816(float c[4], const uint32_t a[4],
                                         const uint32_t b[2]) {
    asm volatile(
        "mma.sync.aligned.m16n8k16.row.col.f32.bf16.bf16.f32 "
        "{%0,%1,%2,%3}, {%4,%5,%6,%7}, {%8,%9}, {%0,%1,%2,%3};"
        : "+f"(c[0]), "+f"(c[1]), "+f"(c[2]), "+f"(c[3])
        : "r"(a[0]), "r"(a[1]), "r"(a[2]), "r"(a[3]), "r"(b[0]), "r"(b[1]));
}
// split fp32 pair into (hi, lo) packed bf16x2
__device__ __forceinline__ void split_pair(float x, float y,
                                           uint32_t& hi, uint32_t& lo) {
    __nv_bfloat16 hx = __float2bfloat16(x);
    __nv_bfloat16 hy = __float2bfloat16(y);
    float rx = x - __bfloat162float(hx);
    float ry = y - __bfloat162float(hy);
    __nv_bfloat162 hp = __halves2bfloat162(hx, hy);
    __nv_bfloat162 lp = __floats2bfloat162_rn(rx, ry);
    hi = *reinterpret_cast<uint32_t*>(&hp);
    lo = *reinterpret_cast<uint32_t*>(&lp);
}

// ===========================================================================
// Split-bf16 HMMA GEMM with bias: C[M,N] = A[M,K] @ B[K,N] + bias[N]
//   CTA 128x128, BK=32, 8 warps (2m x 4n), warp tile 64x32.
//   A smem [m][k] pitch 40 bf16 (80 B); B smem [k][n] pitch 136 bf16 (272 B).
//   A*B ~= Ahi*Bhi + Alo*Bhi + Ahi*Blo, fp32 accumulators.
// Requirements: M % 128 == 0, K % 32 == 0; N guarded (float4 granularity).
// ===========================================================================
#define SA_HI_OFF 0
#define SA_LO_OFF 10240
#define SB_HI_OFF 20480
#define SB_LO_OFF 29184
#define EP_PITCH  132
#define GEMM_SMEM_BYTES (128 * EP_PITCH * 4)   // 67584 (> mainloop 37888)

__global__ void __launch_bounds__(256) hmma_gemm_bias(
    const float* __restrict__ A, const float* __restrict__ B,
    const float* __restrict__ bias, float* __restrict__ C,
    int M, int N, int K)
{
    extern __shared__ char smem[];
    const uint32_t sb = smem_u32(smem);
    const int tid = threadIdx.x, lane = tid & 31, wid = tid >> 5;
    const int wm = wid >> 2, wn = wid & 3;
    const int m0 = blockIdx.y * 128, n0 = blockIdx.x * 128;

    float acc[4][4][4];
    #pragma unroll
    for (int mi = 0; mi < 4; mi++)
        #pragma unroll
        for (int ni = 0; ni < 4; ni++)
            #pragma unroll
            for (int q = 0; q < 4; q++) acc[mi][ni][q] = 0.f;

    float4 stA[4], stB[4];
    // prologue: load chunk 0 into registers
    #pragma unroll
    for (int r = 0; r < 4; r++) {
        int i = tid + r * 256;
        int m = i >> 3, kq = (i & 7) * 4;
        stA[r] = *(const float4*)(A + (size_t)(m0 + m) * K + kq);
    }
    #pragma unroll
    for (int r = 0; r < 4; r++) {
        int i = tid + r * 256;
        int k = i >> 5, nq = (i & 31) * 4;
        stB[r] = (n0 + nq < N) ? *(const float4*)(B + (size_t)k * N + n0 + nq)
                               : make_float4(0.f, 0.f, 0.f, 0.f);
    }

    const int nch = K >> 5;
    for (int ch = 0; ch < nch; ch++) {
        __syncthreads();   // prior chunk's ldmatrix reads done before overwrite
        // convert + store stage
        #pragma unroll
        for (int r = 0; r < 4; r++) {
            int i = tid + r * 256;
            int m = i >> 3, kq = (i & 7) * 4;
            uint32_t h0, l0, h1, l1;
            split_pair(stA[r].x, stA[r].y, h0, l0);
            split_pair(stA[r].z, stA[r].w, h1, l1);
            uint32_t off = (uint32_t)m * 80u + (uint32_t)kq * 2u;
            *(uint2*)(smem + SA_HI_OFF + off) = make_uint2(h0, h1);
            *(uint2*)(smem + SA_LO_OFF + off) = make_uint2(l0, l1);
        }
        #pragma unroll
        for (int r = 0; r < 4; r++) {
            int i = tid + r * 256;
            int k = i >> 5, nq = (i & 31) * 4;
            uint32_t h0, l0, h1, l1;
            split_pair(stB[r].x, stB[r].y, h0, l0);
            split_pair(stB[r].z, stB[r].w, h1, l1);
            uint32_t off = (uint32_t)k * 272u + (uint32_t)nq * 2u;
            *(uint2*)(smem + SB_HI_OFF + off) = make_uint2(h0, h1);
            *(uint2*)(smem + SB_LO_OFF + off) = make_uint2(l0, l1);
        }
        __syncthreads();

        // prefetch next chunk (LDG latency hides under MMA below)
        if (ch + 1 < nch) {
            const int k0n = (ch + 1) * 32;
            #pragma unroll
            for (int r = 0; r < 4; r++) {
                int i = tid + r * 256;
                int m = i >> 3, kq = (i & 7) * 4;
                stA[r] = *(const float4*)(A + (size_t)(m0 + m) * K + k0n + kq);
            }
            #pragma unroll
            for (int r = 0; r < 4; r++) {
                int i = tid + r * 256;
                int k = i >> 5, nq = (i & 31) * 4;
                stB[r] = (n0 + nq < N)
                    ? *(const float4*)(B + (size_t)(k0n + k) * N + n0 + nq)
                    : make_float4(0.f, 0.f, 0.f, 0.f);
            }
        }

        // MMA over two k16 steps
        #pragma unroll
        for (int s = 0; s < 2; s++) {
            uint32_t ah[4][4], al[4][4], bh[4][2], bl[4][2];
            const uint32_t arow  = (uint32_t)(lane & 15);
            const uint32_t acolb = (uint32_t)(s * 32 + (lane >> 4) * 16);
            #pragma unroll
            for (int mi = 0; mi < 4; mi++) {
                uint32_t addr = sb + SA_HI_OFF
                              + (uint32_t)(wm * 64 + mi * 16 + arow) * 80u + acolb;
                ldsm_x4(ah[mi], addr);
                ldsm_x4(al[mi], addr + (SA_LO_OFF - SA_HI_OFF));
            }
            const uint32_t brow = (uint32_t)(s * 16 + (lane & 15));
            #pragma unroll
            for (int ni = 0; ni < 4; ni++) {
                uint32_t addr = sb + SB_HI_OFF + brow * 272u
                              + (uint32_t)(wn * 32 + ni * 8) * 2u;
                ldsm_x2t(bh[ni], addr);
                ldsm_x2t(bl[ni], addr + (SB_LO_OFF - SB_HI_OFF));
            }
            #pragma unroll
            for (int mi = 0; mi < 4; mi++)
                #pragma unroll
                for (int ni = 0; ni < 4; ni++) {
                    mma16816(acc[mi][ni], ah[mi], bh[ni]);
                    mma16816(acc[mi][ni], al[mi], bh[ni]);
                    mma16816(acc[mi][ni], ah[mi], bl[ni]);
                }
        }
    }
    __syncthreads();

    // ---- epilogue: regs -> smem (pad 132) -> coalesced float4 STG + bias ----
    float* ep = (float*)smem;
    #pragma unroll
    for (int mi = 0; mi < 4; mi++) {
        int r0 = wm * 64 + mi * 16 + (lane >> 2);
        #pragma unroll
        for (int ni = 0; ni < 4; ni++) {
            int c = wn * 32 + ni * 8 + (lane & 3) * 2;
            ep[r0 * EP_PITCH + c]           = acc[mi][ni][0];
            ep[r0 * EP_PITCH + c + 1]       = acc[mi][ni][1];
            ep[(r0 + 8) * EP_PITCH + c]     = acc[mi][ni][2];
            ep[(r0 + 8) * EP_PITCH + c + 1] = acc[mi][ni][3];
        }
    }
    __syncthreads();
    for (int i = tid; i < 4096; i += 256) {
        int r = i >> 5, cq = (i & 31) * 4;
        int col = n0 + cq;
        if (col < N) {
            float4 b4 = *(const float4*)(bias + col);
            float4 o;
            o.x = ep[r * EP_PITCH + cq + 0] + b4.x;
            o.y = ep[r * EP_PITCH + cq + 1] + b4.y;
            o.z = ep[r * EP_PITCH + cq + 2] + b4.z;
            o.w = ep[r * EP_PITCH + cq + 3] + b4.w;
            *(float4*)(C + (size_t)(m0 + r) * N + col) = o;
        }
    }
}

// ---------------------------------------------------------------------------
// RoPE inv_freq table init: 32 threads, double-precision YaRN formula (same
// numerics as before), run ONCE per launch instead of per (t, head, i).
// ---------------------------------------------------------------------------
__global__ void rope_table_kernel(float* __restrict__ invf_out)
{
    const int i = threadIdx.x;   // 0..31
    const double lgbase = log(150000.0);
    const double low  = 32.0 * log(1024.0 / (32.0 * 2.0 * M_PI)) / lgbase;
    const double high = 32.0 * log(1024.0 / ( 1.0 * 2.0 * M_PI)) / lgbase;
    double freq = pow(150000.0, (double)(2 * i) / 64.0);
    double ramp = ((double)i - low) / (high - low);
    ramp = fmin(1.0, fmax(0.0, ramp));
    double invf = ramp / (32.0 * freq) + (1.0 - ramp) / freq;
    invf_out[i] = (float)invf;
}

// ---------------------------------------------------------------------------
// RoPE apply (pure fp32): reads table, rotates q/k halves in place.
// ---------------------------------------------------------------------------
__global__ void rope_kernel(float* __restrict__ qkv,
                            const float* __restrict__ invf)
{
    const int t  = blockIdx.x;
    const int hh = blockIdx.y * blockDim.y + threadIdx.y;   // 0..71
    if (hh >= NH + NKV) return;
    const int i = threadIdx.x;                               // 0..31

    float ang = (float)t * __ldg(&invf[i]);
    const float conc = 0.1f * logf(32.0f) + 1.0f;
    float s, c;
    sincosf(ang, &s, &c);
    c *= conc; s *= conc;

    float* p = qkv + (size_t)t * QKV_DIM
             + (hh < NH ? hh * HD : QDIM + (hh - NH) * HD);
    float x1 = p[i], x2 = p[i + 32];
    p[i]      = x1 * c - x2 * s;
    p[i + 32] = x2 * c + x1 * s;
}

// ---------------------------------------------------------------------------
// Sliding-window GQA attention with sink logits.
// ---------------------------------------------------------------------------
#define KV_PITCH 65

__global__ void __launch_bounds__(256) attn_kernel(
    const float* __restrict__ qkv, const float* __restrict__ sinks,
    float* __restrict__ attn)
{
    extern __shared__ float sm[];
    float* Ks = sm;                       // WIN * 65
    float* Vs = Ks + WIN * KV_PITCH;      // WIN * 65
    float* qs = Vs + WIN * KV_PITCH;      // 8 * 64
    float* ws = qs + NKV * HD;            // 8 * 128

    const int t   = blockIdx.x;
    const int hkv = blockIdx.y;
    const int j0  = max(0, t - (WIN - 1));
    const int cnt = t - j0 + 1;
    const int tid = threadIdx.x;

    for (int idx = tid; idx < cnt * HD; idx += 256) {
        int j = idx >> 6, d = idx & 63;
        const float* row = qkv + (size_t)(j0 + j) * QKV_DIM + hkv * HD;
        Ks[j * KV_PITCH + d] = row[QDIM + d];
        Vs[j * KV_PITCH + d] = row[QDIM + NKV * HD + d];
    }
    for (int idx = tid; idx < 8 * HD; idx += 256)
        qs[idx] = qkv[(size_t)t * QKV_DIM + hkv * (8 * HD) + idx];
    __syncthreads();

    const int warp = tid >> 5;
    const int lane = tid & 31;

    float sc[4];
    float mmax = -INFINITY;
    #pragma unroll
    for (int r = 0; r < 4; r++) {
        int j = lane + r * 32;
        if (j < cnt) {
            const float* kr = &Ks[j * KV_PITCH];
            const float* qr = &qs[warp * HD];
            float dot = 0.f;
            #pragma unroll
            for (int d = 0; d < HD; d++) dot = fmaf(qr[d], kr[d], dot);
            sc[r] = dot * SM_SCALE;
            mmax = fmaxf(mmax, sc[r]);
        } else {
            sc[r] = -INFINITY;
        }
    }
    #pragma unroll
    for (int o = 16; o; o >>= 1) mmax = fmaxf(mmax, __shfl_xor_sync(~0u, mmax, o));

    float ssum = 0.f;
    #pragma unroll
    for (int r = 0; r < 4; r++) {
        float e = (sc[r] == -INFINITY) ? 0.f : expf(sc[r] - mmax);
        sc[r] = e;
        ssum += e;
    }
    #pragma unroll
    for (int o = 16; o; o >>= 1) ssum += __shfl_xor_sync(~0u, ssum, o);

    const float denom = ssum + expf(sinks[hkv * 8 + warp] - mmax);
    const float invd = 1.f / denom;

    #pragma unroll
    for (int r = 0; r < 4; r++) {
        int j = lane + r * 32;
        if (j < cnt) ws[warp * WIN + j] = sc[r] * invd;
    }
    __syncwarp();

    #pragma unroll
    for (int d2 = 0; d2 < 2; d2++) {
        int d = lane + d2 * 32;
        float acc = 0.f;
        for (int j = 0; j < cnt; j++)
            acc = fmaf(ws[warp * WIN + j], Vs[j * KV_PITCH + d], acc);
        attn[(size_t)t * QDIM + hkv * (8 * HD) + warp * HD + d] = acc;
    }
}

// ---------------------------------------------------------------------------
extern "C" void kernel_launch(void* const* d_in, const int* in_sizes, int n_in,
                              void* d_out, int out_size)
{
    const float* x      = (const float*)d_in[0];
    const float* W_qkv  = (const float*)d_in[1];
    const float* b_qkv  = (const float*)d_in[2];
    const float* W_out  = (const float*)d_in[3];
    const float* b_out  = (const float*)d_in[4];
    const float* sinks  = (const float*)d_in[5];
    float* out = (float*)d_out;

    float *qkv_ptr, *attn_ptr, *invf_ptr;
    cudaGetSymbolAddress((void**)&qkv_ptr, g_qkv);
    cudaGetSymbolAddress((void**)&attn_ptr, g_attn);
    cudaGetSymbolAddress((void**)&invf_ptr, g_invf);

    cudaFuncSetAttribute(hmma_gemm_bias,
                         cudaFuncAttributeMaxDynamicSharedMemorySize,
                         GEMM_SMEM_BYTES);
    const int attn_smem = (WIN * KV_PITCH * 2 + NKV * HD + 8 * WIN) * (int)sizeof(float);
    cudaFuncSetAttribute(attn_kernel, cudaFuncAttributeMaxDynamicSharedMemorySize,
                         attn_smem);

    // 0) rope inv_freq table (32 threads, once)
    rope_table_kernel<<<1, 32>>>(invf_ptr);

    // 1) qkv = x @ W_qkv + b_qkv          (1536 x 5120, K=2880)
    {
        dim3 grid(QKV_DIM / 128, T_SEQ / 128);
        hmma_gemm_bias<<<grid, 256, GEMM_SMEM_BYTES>>>(
            x, W_qkv, b_qkv, qkv_ptr, T_SEQ, QKV_DIM, D_MODEL);
    }
    // 2) RoPE in place on q,k slices (fp32, table-based)
    {
        dim3 grid(T_SEQ, 9);
        dim3 block(32, 8);
        rope_kernel<<<grid, block>>>(qkv_ptr, invf_ptr);
    }
    // 3) sliding-window GQA attention with sinks
    {
        dim3 grid(T_SEQ, NKV);
        attn_kernel<<<grid, 256, attn_smem>>>(qkv_ptr, sinks, attn_ptr);
    }
    // 4) out = attn @ W_out + b_out       (1536 x 2880, K=4096)
    {
        dim3 grid((D_MODEL + 127) / 128, T_SEQ / 128);
        hmma_gemm_bias<<<grid, 256, GEMM_SMEM_BYTES>>>(
            attn_ptr, W_out, b_out, out, T_SEQ, D_MODEL, QDIM);
    }
}

// round 8
// speedup vs baseline: 3.3424x; 1.0589x over previous
#include <cuda_runtime.h>
#include <cuda_bf16.h>
#include <math.h>
#include <cstdint>

// Problem dims (fixed by reference)
#define T_SEQ   1536
#define D_MODEL 2880
#define NH      64
#define NKV     8
#define HD      64
#define QKV_DIM 5120          // 64*(64+16)
#define QDIM    4096          // NH*HD
#define WIN     128
#define SM_SCALE 0.125f

// Scratch (allocation-free rule: device globals)
__device__ float g_qkv[T_SEQ * QKV_DIM];   // 31.4 MB
__device__ float g_attn[T_SEQ * QDIM];     // 25.2 MB
__device__ float g_invf[32];               // rope inv_freq table

// ===========================================================================
// HMMA (mma.sync) helpers — plain sm_80+ PTX, assembles for .target sm_103
// ===========================================================================
__device__ __forceinline__ uint32_t smem_u32(const void* p) {
    uint32_t a;
    asm("{ .reg .u64 t; cvta.to.shared.u64 t, %1; cvt.u32.u64 %0, t; }"
        : "=r"(a) : "l"(p));
    return a;
}
__device__ __forceinline__ void ldsm_x4(uint32_t r[4], uint32_t a) {
    asm volatile("ldmatrix.sync.aligned.m8n8.x4.shared.b16 {%0,%1,%2,%3}, [%4];"
        : "=r"(r[0]), "=r"(r[1]), "=r"(r[2]), "=r"(r[3]) : "r"(a));
}
__device__ __forceinline__ void ldsm_x2t(uint32_t r[2], uint32_t a) {
    asm volatile("ldmatrix.sync.aligned.m8n8.x2.trans.shared.b16 {%0,%1}, [%2];"
        : "=r"(r[0]), "=r"(r[1]) : "r"(a));
}
__device__ __forceinline__ void mma16816(float c[4], const uint32_t a[4],
                                         const uint32_t b[2]) {
    asm volatile(
        "mma.sync.aligned.m16n8k16.row.col.f32.bf16.bf16.f32 "
        "{%0,%1,%2,%3}, {%4,%5,%6,%7}, {%8,%9}, {%0,%1,%2,%3};"
        : "+f"(c[0]), "+f"(c[1]), "+f"(c[2]), "+f"(c[3])
        : "r"(a[0]), "r"(a[1]), "r"(a[2]), "r"(a[3]), "r"(b[0]), "r"(b[1]));
}
// split fp32 pair into (hi, lo) packed bf16x2
__device__ __forceinline__ void split_pair(float x, float y,
                                           uint32_t& hi, uint32_t& lo) {
    __nv_bfloat16 hx = __float2bfloat16(x);
    __nv_bfloat16 hy = __float2bfloat16(y);
    float rx = x - __bfloat162float(hx);
    float ry = y - __bfloat162float(hy);
    __nv_bfloat162 hp = __halves2bfloat162(hx, hy);
    __nv_bfloat162 lp = __floats2bfloat162_rn(rx, ry);
    hi = *reinterpret_cast<uint32_t*>(&hp);
    lo = *reinterpret_cast<uint32_t*>(&lp);
}

// ===========================================================================
// Split-bf16 HMMA GEMM with bias, double-buffered smem.
//   C[M,N] = A[M,K] @ B[K,N] + bias[N]
//   CTA 128x128, BK=32, 8 warps (2m x 4n), warp tile 64x32.
//   A smem [m][k] pitch 80 B; B smem [k][n] pitch 272 B.
//   A*B ~= Ahi*Bhi + Alo*Bhi + Ahi*Blo, fp32 accumulators.
// ===========================================================================
#define SA_HI_OFF 0
#define SA_LO_OFF 10240
#define SB_HI_OFF 20480
#define SB_LO_OFF 29184
#define BUF_STRIDE 37888
#define EP_PITCH  132
#define GEMM_SMEM_BYTES (2 * BUF_STRIDE)   // 75776 (epilogue 67584 aliases)

__global__ void __launch_bounds__(256) hmma_gemm_bias(
    const float* __restrict__ A, const float* __restrict__ B,
    const float* __restrict__ bias, float* __restrict__ C,
    int M, int N, int K)
{
    extern __shared__ char smem[];
    const uint32_t sb = smem_u32(smem);
    const int tid = threadIdx.x, lane = tid & 31, wid = tid >> 5;
    const int wm = wid >> 2, wn = wid & 3;
    const int m0 = blockIdx.y * 128, n0 = blockIdx.x * 128;

    float acc[4][4][4];
    #pragma unroll
    for (int mi = 0; mi < 4; mi++)
        #pragma unroll
        for (int ni = 0; ni < 4; ni++)
            #pragma unroll
            for (int q = 0; q < 4; q++) acc[mi][ni][q] = 0.f;

    // thread's fixed tile coordinates for loads
    const int amr = tid >> 3, akq = (tid & 7) * 4;        // A: 4 rows of 32 apart? no:
    // A mapping: i = tid + r*256 -> m = i>>3 (0..127), kq = (i&7)*4
    // B mapping: i = tid + r*256 -> k = i>>5 (0..31),  nq = (i&31)*4

    float4 stA[4], stB[4];
    auto ldg_chunk = [&](int k0) {
        #pragma unroll
        for (int r = 0; r < 4; r++) {
            int i = tid + r * 256;
            int m = i >> 3, kq = (i & 7) * 4;
            stA[r] = *(const float4*)(A + (size_t)(m0 + m) * K + k0 + kq);
        }
        #pragma unroll
        for (int r = 0; r < 4; r++) {
            int i = tid + r * 256;
            int k = i >> 5, nq = (i & 31) * 4;
            stB[r] = (n0 + nq < N)
                ? *(const float4*)(B + (size_t)(k0 + k) * N + n0 + nq)
                : make_float4(0.f, 0.f, 0.f, 0.f);
        }
    };
    auto sts_chunk = [&](int buf) {
        char* base = smem + buf * BUF_STRIDE;
        #pragma unroll
        for (int r = 0; r < 4; r++) {
            int i = tid + r * 256;
            int m = i >> 3, kq = (i & 7) * 4;
            uint32_t h0, l0, h1, l1;
            split_pair(stA[r].x, stA[r].y, h0, l0);
            split_pair(stA[r].z, stA[r].w, h1, l1);
            uint32_t off = (uint32_t)m * 80u + (uint32_t)kq * 2u;
            *(uint2*)(base + SA_HI_OFF + off) = make_uint2(h0, h1);
            *(uint2*)(base + SA_LO_OFF + off) = make_uint2(l0, l1);
        }
        #pragma unroll
        for (int r = 0; r < 4; r++) {
            int i = tid + r * 256;
            int k = i >> 5, nq = (i & 31) * 4;
            uint32_t h0, l0, h1, l1;
            split_pair(stB[r].x, stB[r].y, h0, l0);
            split_pair(stB[r].z, stB[r].w, h1, l1);
            uint32_t off = (uint32_t)k * 272u + (uint32_t)nq * 2u;
            *(uint2*)(base + SB_HI_OFF + off) = make_uint2(h0, h1);
            *(uint2*)(base + SB_LO_OFF + off) = make_uint2(l0, l1);
        }
    };

    const int nch = K >> 5;
    // prologue: chunk 0 -> buf 0
    ldg_chunk(0);
    sts_chunk(0);
    __syncthreads();

    for (int ch = 0; ch < nch; ch++) {
        const uint32_t bufb = sb + (uint32_t)(ch & 1) * BUF_STRIDE;

        // issue gmem loads for next chunk (latency hides under MMA)
        if (ch + 1 < nch) ldg_chunk((ch + 1) * 32);

        // MMA over two k16 steps from current buffer
        #pragma unroll
        for (int s = 0; s < 2; s++) {
            uint32_t ah[4][4], al[4][4], bh[4][2], bl[4][2];
            const uint32_t arow  = (uint32_t)(lane & 15);
            const uint32_t acolb = (uint32_t)(s * 32 + (lane >> 4) * 16);
            #pragma unroll
            for (int mi = 0; mi < 4; mi++) {
                uint32_t addr = bufb + SA_HI_OFF
                              + (uint32_t)(wm * 64 + mi * 16 + arow) * 80u + acolb;
                ldsm_x4(ah[mi], addr);
                ldsm_x4(al[mi], addr + (SA_LO_OFF - SA_HI_OFF));
            }
            const uint32_t brow = (uint32_t)(s * 16 + (lane & 15));
            #pragma unroll
            for (int ni = 0; ni < 4; ni++) {
                uint32_t addr = bufb + SB_HI_OFF + brow * 272u
                              + (uint32_t)(wn * 32 + ni * 8) * 2u;
                ldsm_x2t(bh[ni], addr);
                ldsm_x2t(bl[ni], addr + (SB_LO_OFF - SB_HI_OFF));
            }
            #pragma unroll
            for (int mi = 0; mi < 4; mi++)
                #pragma unroll
                for (int ni = 0; ni < 4; ni++) {
                    mma16816(acc[mi][ni], ah[mi], bh[ni]);
                    mma16816(acc[mi][ni], al[mi], bh[ni]);
                    mma16816(acc[mi][ni], ah[mi], bl[ni]);
                }
        }

        // convert + store next chunk into the other buffer (overlaps tensor)
        if (ch + 1 < nch) sts_chunk((ch + 1) & 1);
        __syncthreads();
    }

    // ---- epilogue: regs -> smem (pad 132) -> coalesced float4 STG + bias ----
    float* ep = (float*)smem;
    #pragma unroll
    for (int mi = 0; mi < 4; mi++) {
        int r0 = wm * 64 + mi * 16 + (lane >> 2);
        #pragma unroll
        for (int ni = 0; ni < 4; ni++) {
            int c = wn * 32 + ni * 8 + (lane & 3) * 2;
            ep[r0 * EP_PITCH + c]           = acc[mi][ni][0];
            ep[r0 * EP_PITCH + c + 1]       = acc[mi][ni][1];
            ep[(r0 + 8) * EP_PITCH + c]     = acc[mi][ni][2];
            ep[(r0 + 8) * EP_PITCH + c + 1] = acc[mi][ni][3];
        }
    }
    __syncthreads();
    for (int i = tid; i < 4096; i += 256) {
        int r = i >> 5, cq = (i & 31) * 4;
        int col = n0 + cq;
        if (col < N) {
            float4 b4 = *(const float4*)(bias + col);
            float4 o;
            o.x = ep[r * EP_PITCH + cq + 0] + b4.x;
            o.y = ep[r * EP_PITCH + cq + 1] + b4.y;
            o.z = ep[r * EP_PITCH + cq + 2] + b4.z;
            o.w = ep[r * EP_PITCH + cq + 3] + b4.w;
            *(float4*)(C + (size_t)(m0 + r) * N + col) = o;
        }
    }
}

// ---------------------------------------------------------------------------
// RoPE inv_freq table init (32 threads, double precision, once per launch)
// ---------------------------------------------------------------------------
__global__ void rope_table_kernel(float* __restrict__ invf_out)
{
    const int i = threadIdx.x;   // 0..31
    const double lgbase = log(150000.0);
    const double low  = 32.0 * log(1024.0 / (32.0 * 2.0 * M_PI)) / lgbase;
    const double high = 32.0 * log(1024.0 / ( 1.0 * 2.0 * M_PI)) / lgbase;
    double freq = pow(150000.0, (double)(2 * i) / 64.0);
    double ramp = ((double)i - low) / (high - low);
    ramp = fmin(1.0, fmax(0.0, ramp));
    double invf = ramp / (32.0 * freq) + (1.0 - ramp) / freq;
    invf_out[i] = (float)invf;
}

// ---------------------------------------------------------------------------
// RoPE apply (pure fp32): reads table, rotates q/k halves in place.
// ---------------------------------------------------------------------------
__global__ void rope_kernel(float* __restrict__ qkv,
                            const float* __restrict__ invf)
{
    const int t  = blockIdx.x;
    const int hh = blockIdx.y * blockDim.y + threadIdx.y;   // 0..71
    if (hh >= NH + NKV) return;
    const int i = threadIdx.x;                               // 0..31

    float ang = (float)t * __ldg(&invf[i]);
    const float conc = 0.1f * logf(32.0f) + 1.0f;
    float s, c;
    sincosf(ang, &s, &c);
    c *= conc; s *= conc;

    float* p = qkv + (size_t)t * QKV_DIM
             + (hh < NH ? hh * HD : QDIM + (hh - NH) * HD);
    float x1 = p[i], x2 = p[i + 32];
    p[i]      = x1 * c - x2 * s;
    p[i + 32] = x2 * c + x1 * s;
}

// ---------------------------------------------------------------------------
// Sliding-window GQA attention with sink logits.
// Block = (token t, kv head). 8 warps = 8 q heads. q held in registers,
// K read as float4 (pitch 17 float4 = 68 floats, odd -> conflict-free),
// V read as float2.
// ---------------------------------------------------------------------------
#define KVP4 17          // float4 pitch
#define KVPF 68          // float pitch
#define ATTN_SMEM ((2 * WIN * KVPF + 8 * WIN) * 4)   // 73728 B

__global__ void __launch_bounds__(256) attn_kernel(
    const float* __restrict__ qkv, const float* __restrict__ sinks,
    float* __restrict__ attn)
{
    extern __shared__ float sm[];
    float4* Ks4 = (float4*)sm;                    // WIN * 17 float4
    float4* Vs4 = Ks4 + WIN * KVP4;               // WIN * 17 float4
    float*  ws  = sm + 2 * WIN * KVPF;            // 8 * 128

    const int t   = blockIdx.x;
    const int hkv = blockIdx.y;
    const int j0  = max(0, t - (WIN - 1));
    const int cnt = t - j0 + 1;
    const int tid = threadIdx.x;
    const int warp = tid >> 5;
    const int lane = tid & 31;

    // fill K/V window (float4 coalesced)
    for (int i = tid; i < cnt * 16; i += 256) {
        int j = i >> 4, d4 = i & 15;
        const float* row = qkv + (size_t)(j0 + j) * QKV_DIM + QDIM + hkv * HD;
        Ks4[j * KVP4 + d4] = ((const float4*)row)[d4];
        Vs4[j * KVP4 + d4] = ((const float4*)(row + NKV * HD))[d4];
    }

    // q for this warp's head: all 64 floats in registers (broadcast loads)
    float4 q4[16];
    {
        const float4* qp = (const float4*)(qkv + (size_t)t * QKV_DIM
                                           + (hkv * 8 + warp) * HD);
        #pragma unroll
        for (int d4 = 0; d4 < 16; d4++) q4[d4] = __ldg(&qp[d4]);
    }
    __syncthreads();

    // scores: each lane handles up to 4 positions
    float sc[4];
    float mmax = -INFINITY;
    #pragma unroll
    for (int r = 0; r < 4; r++) {
        int j = lane + r * 32;
        const float4* kr = &Ks4[j * KVP4];
        float dot = 0.f;
        #pragma unroll
        for (int d4 = 0; d4 < 16; d4++) {
            float4 k = kr[d4];
            dot = fmaf(q4[d4].x, k.x, dot);
            dot = fmaf(q4[d4].y, k.y, dot);
            dot = fmaf(q4[d4].z, k.z, dot);
            dot = fmaf(q4[d4].w, k.w, dot);
        }
        sc[r] = (j < cnt) ? dot * SM_SCALE : -INFINITY;
        mmax = fmaxf(mmax, sc[r]);
    }
    #pragma unroll
    for (int o = 16; o; o >>= 1) mmax = fmaxf(mmax, __shfl_xor_sync(~0u, mmax, o));

    float ssum = 0.f;
    #pragma unroll
    for (int r = 0; r < 4; r++) {
        float e = (sc[r] == -INFINITY) ? 0.f : expf(sc[r] - mmax);
        sc[r] = e;
        ssum += e;
    }
    #pragma unroll
    for (int o = 16; o; o >>= 1) ssum += __shfl_xor_sync(~0u, ssum, o);

    const float denom = ssum + expf(sinks[hkv * 8 + warp] - mmax);
    const float invd = 1.f / denom;

    #pragma unroll
    for (int r = 0; r < 4; r++) {
        int j = lane + r * 32;
        if (j < cnt) ws[warp * WIN + j] = sc[r] * invd;
    }
    __syncwarp();

    // PV: each lane accumulates 2 consecutive d values (float2 LDS)
    float2 acc = make_float2(0.f, 0.f);
    const float* wrow = &ws[warp * WIN];
    const float2* Vs2 = (const float2*)Vs4;
    #pragma unroll 4
    for (int j = 0; j < cnt; j++) {
        float w = wrow[j];                       // broadcast
        float2 v = Vs2[j * (KVPF / 2) + lane];   // conflict-free
        acc.x = fmaf(w, v.x, acc.x);
        acc.y = fmaf(w, v.y, acc.y);
    }
    float2* orow = (float2*)(attn + (size_t)t * QDIM + hkv * (8 * HD) + warp * HD);
    orow[lane] = acc;
}

// ---------------------------------------------------------------------------
extern "C" void kernel_launch(void* const* d_in, const int* in_sizes, int n_in,
                              void* d_out, int out_size)
{
    const float* x      = (const float*)d_in[0];
    const float* W_qkv  = (const float*)d_in[1];
    const float* b_qkv  = (const float*)d_in[2];
    const float* W_out  = (const float*)d_in[3];
    const float* b_out  = (const float*)d_in[4];
    const float* sinks  = (const float*)d_in[5];
    float* out = (float*)d_out;

    float *qkv_ptr, *attn_ptr, *invf_ptr;
    cudaGetSymbolAddress((void**)&qkv_ptr, g_qkv);
    cudaGetSymbolAddress((void**)&attn_ptr, g_attn);
    cudaGetSymbolAddress((void**)&invf_ptr, g_invf);

    cudaFuncSetAttribute(hmma_gemm_bias,
                         cudaFuncAttributeMaxDynamicSharedMemorySize,
                         GEMM_SMEM_BYTES);
    cudaFuncSetAttribute(attn_kernel, cudaFuncAttributeMaxDynamicSharedMemorySize,
                         ATTN_SMEM);

    // 0) rope inv_freq table (32 threads, once)
    rope_table_kernel<<<1, 32>>>(invf_ptr);

    // 1) qkv = x @ W_qkv + b_qkv          (1536 x 5120, K=2880)
    {
        dim3 grid(QKV_DIM / 128, T_SEQ / 128);
        hmma_gemm_bias<<<grid, 256, GEMM_SMEM_BYTES>>>(
            x, W_qkv, b_qkv, qkv_ptr, T_SEQ, QKV_DIM, D_MODEL);
    }
    // 2) RoPE in place on q,k slices (fp32, table-based)
    {
        dim3 grid(T_SEQ, 9);
        dim3 block(32, 8);
        rope_kernel<<<grid, block>>>(qkv_ptr, invf_ptr);
    }
    // 3) sliding-window GQA attention with sinks
    {
        dim3 grid(T_SEQ, NKV);
        attn_kernel<<<grid, 256, ATTN_SMEM>>>(qkv_ptr, sinks, attn_ptr);
    }
    // 4) out = attn @ W_out + b_out       (1536 x 2880, K=4096)
    {
        dim3 grid((D_MODEL + 127) / 128, T_SEQ / 128);
        hmma_gemm_bias<<<grid, 256, GEMM_SMEM_BYTES>>>(
            attn_ptr, W_out, b_out, out, T_SEQ, D_MODEL, QDIM);
    }
}

// round 10
// speedup vs baseline: 3.5466x; 1.0611x over previous
#include <cuda_runtime.h>
#include <cuda_bf16.h>
#include <math.h>
#include <cstdint>

// Problem dims (fixed by reference)
#define T_SEQ   1536
#define D_MODEL 2880
#define NH      64
#define NKV     8
#define HD      64
#define QKV_DIM 5120          // 64*(64+16)
#define QDIM    4096          // NH*HD
#define WIN     128
#define SM_SCALE 0.125f

// Scratch (allocation-free rule: device globals)
__device__ float g_qkv[T_SEQ * QKV_DIM];            // fp32 qkv (rope + attn read)
__device__ float g_invf[32];                        // rope inv_freq table
// split-bf16 operands
__device__ __nv_bfloat16 g_xh[T_SEQ * D_MODEL];     // x hi
__device__ __nv_bfloat16 g_xl[T_SEQ * D_MODEL];     // x lo
__device__ __nv_bfloat16 g_wqh[D_MODEL * QKV_DIM];  // W_qkv hi
__device__ __nv_bfloat16 g_wql[D_MODEL * QKV_DIM];  // W_qkv lo
__device__ __nv_bfloat16 g_woh[QDIM * D_MODEL];     // W_out hi
__device__ __nv_bfloat16 g_wol[QDIM * D_MODEL];     // W_out lo
__device__ __nv_bfloat16 g_ath[T_SEQ * QDIM];       // attn out hi
__device__ __nv_bfloat16 g_atl[T_SEQ * QDIM];       // attn out lo

// ===========================================================================
// PTX helpers
// ===========================================================================
__device__ __forceinline__ uint32_t smem_u32(const void* p) {
    uint32_t a;
    asm("{ .reg .u64 t; cvta.to.shared.u64 t, %1; cvt.u32.u64 %0, t; }"
        : "=r"(a) : "l"(p));
    return a;
}
__device__ __forceinline__ void ldsm_x4(uint32_t r[4], uint32_t a) {
    asm volatile("ldmatrix.sync.aligned.m8n8.x4.shared.b16 {%0,%1,%2,%3}, [%4];"
        : "=r"(r[0]), "=r"(r[1]), "=r"(r[2]), "=r"(r[3]) : "r"(a));
}
__device__ __forceinline__ void ldsm_x2t(uint32_t r[2], uint32_t a) {
    asm volatile("ldmatrix.sync.aligned.m8n8.x2.trans.shared.b16 {%0,%1}, [%2];"
        : "=r"(r[0]), "=r"(r[1]) : "r"(a));
}
__device__ __forceinline__ void mma16816(float c[4], const uint32_t a[4],
                                         const uint32_t b[2]) {
    asm volatile(
        "mma.sync.aligned.m16n8k16.row.col.f32.bf16.bf16.f32 "
        "{%0,%1,%2,%3}, {%4,%5,%6,%7}, {%8,%9}, {%0,%1,%2,%3};"
        : "+f"(c[0]), "+f"(c[1]), "+f"(c[2]), "+f"(c[3])
        : "r"(a[0]), "r"(a[1]), "r"(a[2]), "r"(a[3]), "r"(b[0]), "r"(b[1]));
}
__device__ __forceinline__ void cp16(uint32_t saddr, const void* gaddr,
                                     uint32_t srcsize) {
    asm volatile("cp.async.ca.shared.global [%0], [%1], 16, %2;"
        :: "r"(saddr), "l"(gaddr), "r"(srcsize));
}
__device__ __forceinline__ void cp_commit() {
    asm volatile("cp.async.commit_group;" ::: "memory");
}
template <int N>
__device__ __forceinline__ void cp_wait() {
    asm volatile("cp.async.wait_group %0;" :: "n"(N) : "memory");
}
// split fp32 pair into (hi, lo) packed bf16x2
__device__ __forceinline__ void split_pair(float x, float y,
                                           uint32_t& hi, uint32_t& lo) {
    __nv_bfloat16 hx = __float2bfloat16(x);
    __nv_bfloat16 hy = __float2bfloat16(y);
    float rx = x - __bfloat162float(hx);
    float ry = y - __bfloat162float(hy);
    __nv_bfloat162 hp = __halves2bfloat162(hx, hy);
    __nv_bfloat162 lp = __floats2bfloat162_rn(rx, ry);
    hi = *reinterpret_cast<uint32_t*>(&hp);
    lo = *reinterpret_cast<uint32_t*>(&lp);
}

// ===========================================================================
// Split kernel: fp32 -> (hi, lo) bf16, vectorized.
// ===========================================================================
__global__ void __launch_bounds__(256) split_kernel(
    const float4* __restrict__ in, uint2* __restrict__ hi,
    uint2* __restrict__ lo, int n4)
{
    int i = blockIdx.x * 256 + threadIdx.x;
    if (i < n4) {
        float4 v = in[i];
        uint32_t h0, l0, h1, l1;
        split_pair(v.x, v.y, h0, l0);
        split_pair(v.z, v.w, h1, l1);
        hi[i] = make_uint2(h0, h1);
        lo[i] = make_uint2(l0, l1);
    }
}

// ===========================================================================
// Split-bf16 HMMA GEMM with bias (pre-split operands, cp.async pipeline):
//   C[M,N] = (Ah+Al)[M,K] @ (Bh+Bl)[K,N] + bias[N]   (drop Al*Bl)
//   CTA 128x128, BK=32, 8 warps (2m x 4n), warp tile 64x32.
//   A smem [m][k] pitch 80 B; B smem [k][n] pitch 272 B. Double buffered.
// ===========================================================================
#define SA_HI_OFF 0
#define SA_LO_OFF 10240
#define SB_HI_OFF 20480
#define SB_LO_OFF 29184
#define BUF_STRIDE 37888
#define EP_PITCH  132
#define GEMM_SMEM_BYTES (2 * BUF_STRIDE)   // 75776 (epilogue 67584 aliases)

__global__ void __launch_bounds__(256) hmma_gemm_bias(
    const __nv_bfloat16* __restrict__ Ah, const __nv_bfloat16* __restrict__ Al,
    const __nv_bfloat16* __restrict__ Bh, const __nv_bfloat16* __restrict__ Bl,
    const float* __restrict__ bias, float* __restrict__ C,
    int M, int N, int K)
{
    extern __shared__ char smem[];
    const uint32_t sb = smem_u32(smem);
    const int tid = threadIdx.x, lane = tid & 31, wid = tid >> 5;
    const int wm = wid >> 2, wn = wid & 3;
    const int m0 = blockIdx.y * 128, n0 = blockIdx.x * 128;

    float acc[4][4][4];
    #pragma unroll
    for (int mi = 0; mi < 4; mi++)
        #pragma unroll
        for (int ni = 0; ni < 4; ni++)
            #pragma unroll
            for (int q = 0; q < 4; q++) acc[mi][ni][q] = 0.f;

    // per-thread copy coordinates
    const int am  = tid >> 2;            // A row 0..63  (r adds 64)
    const int aks = (tid & 3);           // A 16B-segment 0..3
    const int bk  = tid >> 4;            // B row 0..15  (r adds 16)
    const int bns = (tid & 15);          // B 16B-segment 0..15 (8 cols each)

    auto issue_chunk = [&](int k0, int buf) {
        const uint32_t bb = sb + (uint32_t)buf * BUF_STRIDE;
        #pragma unroll
        for (int r = 0; r < 2; r++) {
            int m = am + r * 64;
            const __nv_bfloat16* ga = Ah + (size_t)(m0 + m) * K + k0 + aks * 8;
            const __nv_bfloat16* gl = Al + (size_t)(m0 + m) * K + k0 + aks * 8;
            uint32_t so = (uint32_t)m * 80u + (uint32_t)aks * 16u;
            cp16(bb + SA_HI_OFF + so, ga, 16);
            cp16(bb + SA_LO_OFF + so, gl, 16);
        }
        #pragma unroll
        for (int r = 0; r < 2; r++) {
            int k = bk + r * 16;
            int ncol = n0 + bns * 8;
            uint32_t sz = (ncol < N) ? 16u : 0u;
            const __nv_bfloat16* gb = Bh + (size_t)(k0 + k) * N + ncol;
            const __nv_bfloat16* gl = Bl + (size_t)(k0 + k) * N + ncol;
            uint32_t so = (uint32_t)k * 272u + (uint32_t)bns * 16u;
            cp16(bb + SB_HI_OFF + so, gb, sz);
            cp16(bb + SB_LO_OFF + so, gl, sz);
        }
        cp_commit();
    };

    const int nch = K >> 5;
    issue_chunk(0, 0);

    for (int ch = 0; ch < nch; ch++) {
        if (ch + 1 < nch) {
            issue_chunk((ch + 1) * 32, (ch + 1) & 1);
            cp_wait<1>();
        } else {
            cp_wait<0>();
        }
        __syncthreads();

        const uint32_t bufb = sb + (uint32_t)(ch & 1) * BUF_STRIDE;
        #pragma unroll
        for (int s = 0; s < 2; s++) {
            uint32_t ah[4][4], al[4][4], bh[4][2], bl[4][2];
            const uint32_t arow  = (uint32_t)(lane & 15);
            const uint32_t acolb = (uint32_t)(s * 32 + (lane >> 4) * 16);
            #pragma unroll
            for (int mi = 0; mi < 4; mi++) {
                uint32_t addr = bufb + SA_HI_OFF
                              + (uint32_t)(wm * 64 + mi * 16 + arow) * 80u + acolb;
                ldsm_x4(ah[mi], addr);
                ldsm_x4(al[mi], addr + (SA_LO_OFF - SA_HI_OFF));
            }
            const uint32_t brow = (uint32_t)(s * 16 + (lane & 15));
            #pragma unroll
            for (int ni = 0; ni < 4; ni++) {
                uint32_t addr = bufb + SB_HI_OFF + brow * 272u
                              + (uint32_t)(wn * 32 + ni * 8) * 2u;
                ldsm_x2t(bh[ni], addr);
                ldsm_x2t(bl[ni], addr + (SB_LO_OFF - SB_HI_OFF));
            }
            #pragma unroll
            for (int mi = 0; mi < 4; mi++)
                #pragma unroll
                for (int ni = 0; ni < 4; ni++) {
                    mma16816(acc[mi][ni], ah[mi], bh[ni]);
                    mma16816(acc[mi][ni], al[mi], bh[ni]);
                    mma16816(acc[mi][ni], ah[mi], bl[ni]);
                }
        }
        __syncthreads();
    }

    // ---- epilogue: regs -> smem (pad 132) -> coalesced float4 STG + bias ----
    float* ep = (float*)smem;
    #pragma unroll
    for (int mi = 0; mi < 4; mi++) {
        int r0 = wm * 64 + mi * 16 + (lane >> 2);
        #pragma unroll
        for (int ni = 0; ni < 4; ni++) {
            int c = wn * 32 + ni * 8 + (lane & 3) * 2;
            ep[r0 * EP_PITCH + c]           = acc[mi][ni][0];
            ep[r0 * EP_PITCH + c + 1]       = acc[mi][ni][1];
            ep[(r0 + 8) * EP_PITCH + c]     = acc[mi][ni][2];
            ep[(r0 + 8) * EP_PITCH + c + 1] = acc[mi][ni][3];
        }
    }
    __syncthreads();
    for (int i = tid; i < 4096; i += 256) {
        int r = i >> 5, cq = (i & 31) * 4;
        int col = n0 + cq;
        if (col < N) {
            float4 b4 = *(const float4*)(bias + col);
            float4 o;
            o.x = ep[r * EP_PITCH + cq + 0] + b4.x;
            o.y = ep[r * EP_PITCH + cq + 1] + b4.y;
            o.z = ep[r * EP_PITCH + cq + 2] + b4.z;
            o.w = ep[r * EP_PITCH + cq + 3] + b4.w;
            *(float4*)(C + (size_t)(m0 + r) * N + col) = o;
        }
    }
}

// ---------------------------------------------------------------------------
// RoPE inv_freq table init (32 threads, double precision, once per launch)
// ---------------------------------------------------------------------------
__global__ void rope_table_kernel(float* __restrict__ invf_out)
{
    const int i = threadIdx.x;   // 0..31
    const double lgbase = log(150000.0);
    const double low  = 32.0 * log(1024.0 / (32.0 * 2.0 * M_PI)) / lgbase;
    const double high = 32.0 * log(1024.0 / ( 1.0 * 2.0 * M_PI)) / lgbase;
    double freq = pow(150000.0, (double)(2 * i) / 64.0);
    double ramp = ((double)i - low) / (high - low);
    ramp = fmin(1.0, fmax(0.0, ramp));
    double invf = ramp / (32.0 * freq) + (1.0 - ramp) / freq;
    invf_out[i] = (float)invf;
}

// ---------------------------------------------------------------------------
// RoPE apply (pure fp32): reads table, rotates q/k halves in place.
// ---------------------------------------------------------------------------
__global__ void rope_kernel(float* __restrict__ qkv,
                            const float* __restrict__ invf)
{
    const int t  = blockIdx.x;
    const int hh = blockIdx.y * blockDim.y + threadIdx.y;   // 0..71
    if (hh >= NH + NKV) return;
    const int i = threadIdx.x;                               // 0..31

    float ang = (float)t * __ldg(&invf[i]);
    const float conc = 0.1f * logf(32.0f) + 1.0f;
    float s, c;
    sincosf(ang, &s, &c);
    c *= conc; s *= conc;

    float* p = qkv + (size_t)t * QKV_DIM
             + (hh < NH ? hh * HD : QDIM + (hh - NH) * HD);
    float x1 = p[i], x2 = p[i + 32];
    p[i]      = x1 * c - x2 * s;
    p[i + 32] = x2 * c + x1 * s;
}

// ---------------------------------------------------------------------------
// Sliding-window GQA attention with sink logits. Writes split-bf16 output
// (GEMM2's A operand) directly.
// ---------------------------------------------------------------------------
#define KVP4 17          // float4 pitch
#define KVPF 68          // float pitch
#define ATTN_SMEM ((2 * WIN * KVPF + 8 * WIN) * 4)   // 73728 B

__global__ void __launch_bounds__(256) attn_kernel(
    const float* __restrict__ qkv, const float* __restrict__ sinks,
    __nv_bfloat16* __restrict__ outh, __nv_bfloat16* __restrict__ outl)
{
    extern __shared__ float sm[];
    float4* Ks4 = (float4*)sm;                    // WIN * 17 float4
    float4* Vs4 = Ks4 + WIN * KVP4;               // WIN * 17 float4
    float*  ws  = sm + 2 * WIN * KVPF;            // 8 * 128

    const int t   = blockIdx.x;
    const int hkv = blockIdx.y;
    const int j0  = max(0, t - (WIN - 1));
    const int cnt = t - j0 + 1;
    const int tid = threadIdx.x;
    const int warp = tid >> 5;
    const int lane = tid & 31;

    for (int i = tid; i < cnt * 16; i += 256) {
        int j = i >> 4, d4 = i & 15;
        const float* row = qkv + (size_t)(j0 + j) * QKV_DIM + QDIM + hkv * HD;
        Ks4[j * KVP4 + d4] = ((const float4*)row)[d4];
        Vs4[j * KVP4 + d4] = ((const float4*)(row + NKV * HD))[d4];
    }

    float4 q4[16];
    {
        const float4* qp = (const float4*)(qkv + (size_t)t * QKV_DIM
                                           + (hkv * 8 + warp) * HD);
        #pragma unroll
        for (int d4 = 0; d4 < 16; d4++) q4[d4] = __ldg(&qp[d4]);
    }
    __syncthreads();

    float sc[4];
    float mmax = -INFINITY;
    #pragma unroll
    for (int r = 0; r < 4; r++) {
        int j = lane + r * 32;
        const float4* kr = &Ks4[j * KVP4];
        float dot = 0.f;
        #pragma unroll
        for (int d4 = 0; d4 < 16; d4++) {
            float4 k = kr[d4];
            dot = fmaf(q4[d4].x, k.x, dot);
            dot = fmaf(q4[d4].y, k.y, dot);
            dot = fmaf(q4[d4].z, k.z, dot);
            dot = fmaf(q4[d4].w, k.w, dot);
        }
        sc[r] = (j < cnt) ? dot * SM_SCALE : -INFINITY;
        mmax = fmaxf(mmax, sc[r]);
    }
    #pragma unroll
    for (int o = 16; o; o >>= 1) mmax = fmaxf(mmax, __shfl_xor_sync(~0u, mmax, o));

    float ssum = 0.f;
    #pragma unroll
    for (int r = 0; r < 4; r++) {
        float e = (sc[r] == -INFINITY) ? 0.f : expf(sc[r] - mmax);
        sc[r] = e;
        ssum += e;
    }
    #pragma unroll
    for (int o = 16; o; o >>= 1) ssum += __shfl_xor_sync(~0u, ssum, o);

    const float denom = ssum + expf(sinks[hkv * 8 + warp] - mmax);
    const float invd = 1.f / denom;

    #pragma unroll
    for (int r = 0; r < 4; r++) {
        int j = lane + r * 32;
        if (j < cnt) ws[warp * WIN + j] = sc[r] * invd;
    }
    __syncwarp();

    float2 acc = make_float2(0.f, 0.f);
    const float* wrow = &ws[warp * WIN];
    const float2* Vs2 = (const float2*)Vs4;
    #pragma unroll 4
    for (int j = 0; j < cnt; j++) {
        float w = wrow[j];
        float2 v = Vs2[j * (KVPF / 2) + lane];
        acc.x = fmaf(w, v.x, acc.x);
        acc.y = fmaf(w, v.y, acc.y);
    }
    // write split bf16 (GEMM2 consumes directly)
    uint32_t hi, lo;
    split_pair(acc.x, acc.y, hi, lo);
    size_t base = (size_t)t * QDIM + hkv * (8 * HD) + warp * HD;
    ((uint32_t*)(outh + base))[lane] = hi;
    ((uint32_t*)(outl + base))[lane] = lo;
}

// ---------------------------------------------------------------------------
extern "C" void kernel_launch(void* const* d_in, const int* in_sizes, int n_in,
                              void* d_out, int out_size)
{
    const float* x      = (const float*)d_in[0];
    const float* W_qkv  = (const float*)d_in[1];
    const float* b_qkv  = (const float*)d_in[2];
    const float* W_out  = (const float*)d_in[3];
    const float* b_out  = (const float*)d_in[4];
    const float* sinks  = (const float*)d_in[5];
    float* out = (float*)d_out;

    float *qkv_ptr, *invf_ptr;
    __nv_bfloat16 *xh, *xl, *wqh, *wql, *woh, *wol, *ath, *atl;
    cudaGetSymbolAddress((void**)&qkv_ptr, g_qkv);
    cudaGetSymbolAddress((void**)&invf_ptr, g_invf);
    cudaGetSymbolAddress((void**)&xh, g_xh);
    cudaGetSymbolAddress((void**)&xl, g_xl);
    cudaGetSymbolAddress((void**)&wqh, g_wqh);
    cudaGetSymbolAddress((void**)&wql, g_wql);
    cudaGetSymbolAddress((void**)&woh, g_woh);
    cudaGetSymbolAddress((void**)&wol, g_wol);
    cudaGetSymbolAddress((void**)&ath, g_ath);
    cudaGetSymbolAddress((void**)&atl, g_atl);

    cudaFuncSetAttribute(hmma_gemm_bias,
                         cudaFuncAttributeMaxDynamicSharedMemorySize,
                         GEMM_SMEM_BYTES);
    cudaFuncSetAttribute(attn_kernel, cudaFuncAttributeMaxDynamicSharedMemorySize,
                         ATTN_SMEM);

    // 0) rope table + split inputs to bf16 hi/lo
    rope_table_kernel<<<1, 32>>>(invf_ptr);
    {
        int n4 = T_SEQ * D_MODEL / 4;
        split_kernel<<<(n4 + 255) / 256, 256>>>(
            (const float4*)x, (uint2*)xh, (uint2*)xl, n4);
        n4 = D_MODEL * QKV_DIM / 4;
        split_kernel<<<(n4 + 255) / 256, 256>>>(
            (const float4*)W_qkv, (uint2*)wqh, (uint2*)wql, n4);
        n4 = QDIM * D_MODEL / 4;
        split_kernel<<<(n4 + 255) / 256, 256>>>(
            (const float4*)W_out, (uint2*)woh, (uint2*)wol, n4);
    }

    // 1) qkv = x @ W_qkv + b_qkv          (1536 x 5120, K=2880)
    {
        dim3 grid(QKV_DIM / 128, T_SEQ / 128);
        hmma_gemm_bias<<<grid, 256, GEMM_SMEM_BYTES>>>(
            xh, xl, wqh, wql, b_qkv, qkv_ptr, T_SEQ, QKV_DIM, D_MODEL);
    }
    // 2) RoPE in place on q,k slices (fp32, table-based)
    {
        dim3 grid(T_SEQ, 9);
        dim3 block(32, 8);
        rope_kernel<<<grid, block>>>(qkv_ptr, invf_ptr);
    }
    // 3) sliding-window GQA attention with sinks -> split bf16
    {
        dim3 grid(T_SEQ, NKV);
        attn_kernel<<<grid, 256, ATTN_SMEM>>>(qkv_ptr, sinks, ath, atl);
    }
    // 4) out = attn @ W_out + b_out       (1536 x 2880, K=4096)
    {
        dim3 grid((D_MODEL + 127) / 128, T_SEQ / 128);
        hmma_gemm_bias<<<grid, 256, GEMM_SMEM_BYTES>>>(
            ath, atl, woh, wol, b_out, out, T_SEQ, D_MODEL, QDIM);
    }
}

// round 11
// speedup vs baseline: 3.6977x; 1.0426x over previous
#include <cuda_runtime.h>
#include <cuda_bf16.h>
#include <math.h>
#include <cstdint>

// Problem dims (fixed by reference)
#define T_SEQ   1536
#define D_MODEL 2880
#define NH      64
#define NKV     8
#define HD      64
#define QKV_DIM 5120          // 64*(64+16)
#define QDIM    4096          // NH*HD
#define WIN     128
#define SM_SCALE 0.125f

// Scratch (allocation-free rule: device globals)
__device__ float g_qkv[T_SEQ * QKV_DIM];            // fp32 qkv (rope + attn read)
__device__ float g_invf[32];                        // rope inv_freq table
// split-bf16 operands
__device__ __nv_bfloat16 g_xh[T_SEQ * D_MODEL];     // x hi
__device__ __nv_bfloat16 g_xl[T_SEQ * D_MODEL];     // x lo
__device__ __nv_bfloat16 g_wqh[D_MODEL * QKV_DIM];  // W_qkv hi
__device__ __nv_bfloat16 g_wql[D_MODEL * QKV_DIM];  // W_qkv lo
__device__ __nv_bfloat16 g_woh[QDIM * D_MODEL];     // W_out hi
__device__ __nv_bfloat16 g_wol[QDIM * D_MODEL];     // W_out lo
__device__ __nv_bfloat16 g_ath[T_SEQ * QDIM];       // attn out hi
__device__ __nv_bfloat16 g_atl[T_SEQ * QDIM];       // attn out lo

// ===========================================================================
// PTX helpers
// ===========================================================================
__device__ __forceinline__ uint32_t smem_u32(const void* p) {
    uint32_t a;
    asm("{ .reg .u64 t; cvta.to.shared.u64 t, %1; cvt.u32.u64 %0, t; }"
        : "=r"(a) : "l"(p));
    return a;
}
__device__ __forceinline__ void ldsm_x4(uint32_t r[4], uint32_t a) {
    asm volatile("ldmatrix.sync.aligned.m8n8.x4.shared.b16 {%0,%1,%2,%3}, [%4];"
        : "=r"(r[0]), "=r"(r[1]), "=r"(r[2]), "=r"(r[3]) : "r"(a));
}
__device__ __forceinline__ void ldsm_x4t(uint32_t r[4], uint32_t a) {
    asm volatile("ldmatrix.sync.aligned.m8n8.x4.trans.shared.b16 {%0,%1,%2,%3}, [%4];"
        : "=r"(r[0]), "=r"(r[1]), "=r"(r[2]), "=r"(r[3]) : "r"(a));
}
__device__ __forceinline__ void ldsm_x2(uint32_t r[2], uint32_t a) {
    asm volatile("ldmatrix.sync.aligned.m8n8.x2.shared.b16 {%0,%1}, [%2];"
        : "=r"(r[0]), "=r"(r[1]) : "r"(a));
}
__device__ __forceinline__ void ldsm_x2t(uint32_t r[2], uint32_t a) {
    asm volatile("ldmatrix.sync.aligned.m8n8.x2.trans.shared.b16 {%0,%1}, [%2];"
        : "=r"(r[0]), "=r"(r[1]) : "r"(a));
}
__device__ __forceinline__ void mma16816(float c[4], const uint32_t a[4],
                                         const uint32_t b[2]) {
    asm volatile(
        "mma.sync.aligned.m16n8k16.row.col.f32.bf16.bf16.f32 "
        "{%0,%1,%2,%3}, {%4,%5,%6,%7}, {%8,%9}, {%0,%1,%2,%3};"
        : "+f"(c[0]), "+f"(c[1]), "+f"(c[2]), "+f"(c[3])
        : "r"(a[0]), "r"(a[1]), "r"(a[2]), "r"(a[3]), "r"(b[0]), "r"(b[1]));
}
__device__ __forceinline__ void cp16(uint32_t saddr, const void* gaddr,
                                     uint32_t srcsize) {
    asm volatile("cp.async.ca.shared.global [%0], [%1], 16, %2;"
        :: "r"(saddr), "l"(gaddr), "r"(srcsize));
}
__device__ __forceinline__ void cp_commit() {
    asm volatile("cp.async.commit_group;" ::: "memory");
}
template <int N>
__device__ __forceinline__ void cp_wait() {
    asm volatile("cp.async.wait_group %0;" :: "n"(N) : "memory");
}
// split fp32 pair into (hi, lo) packed bf16x2
__device__ __forceinline__ void split_pair(float x, float y,
                                           uint32_t& hi, uint32_t& lo) {
    __nv_bfloat16 hx = __float2bfloat16(x);
    __nv_bfloat16 hy = __float2bfloat16(y);
    float rx = x - __bfloat162float(hx);
    float ry = y - __bfloat162float(hy);
    __nv_bfloat162 hp = __halves2bfloat162(hx, hy);
    __nv_bfloat162 lp = __floats2bfloat162_rn(rx, ry);
    hi = *reinterpret_cast<uint32_t*>(&hp);
    lo = *reinterpret_cast<uint32_t*>(&lp);
}

// ===========================================================================
// Split kernel: fp32 -> (hi, lo) bf16, vectorized.
// ===========================================================================
__global__ void __launch_bounds__(256) split_kernel(
    const float4* __restrict__ in, uint2* __restrict__ hi,
    uint2* __restrict__ lo, int n4)
{
    int i = blockIdx.x * 256 + threadIdx.x;
    if (i < n4) {
        float4 v = in[i];
        uint32_t h0, l0, h1, l1;
        split_pair(v.x, v.y, h0, l0);
        split_pair(v.z, v.w, h1, l1);
        hi[i] = make_uint2(h0, h1);
        lo[i] = make_uint2(l0, l1);
    }
}

// ===========================================================================
// Split-bf16 HMMA GEMM with bias (pre-split operands, cp.async pipeline)
// ===========================================================================
#define SA_HI_OFF 0
#define SA_LO_OFF 10240
#define SB_HI_OFF 20480
#define SB_LO_OFF 29184
#define BUF_STRIDE 37888
#define EP_PITCH  132
#define GEMM_SMEM_BYTES (2 * BUF_STRIDE)   // 75776 (epilogue 67584 aliases)

__global__ void __launch_bounds__(256) hmma_gemm_bias(
    const __nv_bfloat16* __restrict__ Ah, const __nv_bfloat16* __restrict__ Al,
    const __nv_bfloat16* __restrict__ Bh, const __nv_bfloat16* __restrict__ Bl,
    const float* __restrict__ bias, float* __restrict__ C,
    int M, int N, int K)
{
    extern __shared__ char smem[];
    const uint32_t sb = smem_u32(smem);
    const int tid = threadIdx.x, lane = tid & 31, wid = tid >> 5;
    const int wm = wid >> 2, wn = wid & 3;
    const int m0 = blockIdx.y * 128, n0 = blockIdx.x * 128;

    float acc[4][4][4];
    #pragma unroll
    for (int mi = 0; mi < 4; mi++)
        #pragma unroll
        for (int ni = 0; ni < 4; ni++)
            #pragma unroll
            for (int q = 0; q < 4; q++) acc[mi][ni][q] = 0.f;

    const int am  = tid >> 2;
    const int aks = (tid & 3);
    const int bk  = tid >> 4;
    const int bns = (tid & 15);

    auto issue_chunk = [&](int k0, int buf) {
        const uint32_t bb = sb + (uint32_t)buf * BUF_STRIDE;
        #pragma unroll
        for (int r = 0; r < 2; r++) {
            int m = am + r * 64;
            const __nv_bfloat16* ga = Ah + (size_t)(m0 + m) * K + k0 + aks * 8;
            const __nv_bfloat16* gl = Al + (size_t)(m0 + m) * K + k0 + aks * 8;
            uint32_t so = (uint32_t)m * 80u + (uint32_t)aks * 16u;
            cp16(bb + SA_HI_OFF + so, ga, 16);
            cp16(bb + SA_LO_OFF + so, gl, 16);
        }
        #pragma unroll
        for (int r = 0; r < 2; r++) {
            int k = bk + r * 16;
            int ncol = n0 + bns * 8;
            uint32_t sz = (ncol < N) ? 16u : 0u;
            const __nv_bfloat16* gb = Bh + (size_t)(k0 + k) * N + ncol;
            const __nv_bfloat16* gl = Bl + (size_t)(k0 + k) * N + ncol;
            uint32_t so = (uint32_t)k * 272u + (uint32_t)bns * 16u;
            cp16(bb + SB_HI_OFF + so, gb, sz);
            cp16(bb + SB_LO_OFF + so, gl, sz);
        }
        cp_commit();
    };

    const int nch = K >> 5;
    issue_chunk(0, 0);

    for (int ch = 0; ch < nch; ch++) {
        if (ch + 1 < nch) {
            issue_chunk((ch + 1) * 32, (ch + 1) & 1);
            cp_wait<1>();
        } else {
            cp_wait<0>();
        }
        __syncthreads();

        const uint32_t bufb = sb + (uint32_t)(ch & 1) * BUF_STRIDE;
        #pragma unroll
        for (int s = 0; s < 2; s++) {
            uint32_t ah[4][4], al[4][4], bh[4][2], bl[4][2];
            const uint32_t arow  = (uint32_t)(lane & 15);
            const uint32_t acolb = (uint32_t)(s * 32 + (lane >> 4) * 16);
            #pragma unroll
            for (int mi = 0; mi < 4; mi++) {
                uint32_t addr = bufb + SA_HI_OFF
                              + (uint32_t)(wm * 64 + mi * 16 + arow) * 80u + acolb;
                ldsm_x4(ah[mi], addr);
                ldsm_x4(al[mi], addr + (SA_LO_OFF - SA_HI_OFF));
            }
            const uint32_t brow = (uint32_t)(s * 16 + (lane & 15));
            #pragma unroll
            for (int ni = 0; ni < 4; ni++) {
                uint32_t addr = bufb + SB_HI_OFF + brow * 272u
                              + (uint32_t)(wn * 32 + ni * 8) * 2u;
                ldsm_x2t(bh[ni], addr);
                ldsm_x2t(bl[ni], addr + (SB_LO_OFF - SB_HI_OFF));
            }
            #pragma unroll
            for (int mi = 0; mi < 4; mi++)
                #pragma unroll
                for (int ni = 0; ni < 4; ni++) {
                    mma16816(acc[mi][ni], ah[mi], bh[ni]);
                    mma16816(acc[mi][ni], al[mi], bh[ni]);
                    mma16816(acc[mi][ni], ah[mi], bl[ni]);
                }
        }
        __syncthreads();
    }

    float* ep = (float*)smem;
    #pragma unroll
    for (int mi = 0; mi < 4; mi++) {
        int r0 = wm * 64 + mi * 16 + (lane >> 2);
        #pragma unroll
        for (int ni = 0; ni < 4; ni++) {
            int c = wn * 32 + ni * 8 + (lane & 3) * 2;
            ep[r0 * EP_PITCH + c]           = acc[mi][ni][0];
            ep[r0 * EP_PITCH + c + 1]       = acc[mi][ni][1];
            ep[(r0 + 8) * EP_PITCH + c]     = acc[mi][ni][2];
            ep[(r0 + 8) * EP_PITCH + c + 1] = acc[mi][ni][3];
        }
    }
    __syncthreads();
    for (int i = tid; i < 4096; i += 256) {
        int r = i >> 5, cq = (i & 31) * 4;
        int col = n0 + cq;
        if (col < N) {
            float4 b4 = *(const float4*)(bias + col);
            float4 o;
            o.x = ep[r * EP_PITCH + cq + 0] + b4.x;
            o.y = ep[r * EP_PITCH + cq + 1] + b4.y;
            o.z = ep[r * EP_PITCH + cq + 2] + b4.z;
            o.w = ep[r * EP_PITCH + cq + 3] + b4.w;
            *(float4*)(C + (size_t)(m0 + r) * N + col) = o;
        }
    }
}

// ---------------------------------------------------------------------------
// RoPE inv_freq table init (32 threads, double precision, once per launch)
// ---------------------------------------------------------------------------
__global__ void rope_table_kernel(float* __restrict__ invf_out)
{
    const int i = threadIdx.x;   // 0..31
    const double lgbase = log(150000.0);
    const double low  = 32.0 * log(1024.0 / (32.0 * 2.0 * M_PI)) / lgbase;
    const double high = 32.0 * log(1024.0 / ( 1.0 * 2.0 * M_PI)) / lgbase;
    double freq = pow(150000.0, (double)(2 * i) / 64.0);
    double ramp = ((double)i - low) / (high - low);
    ramp = fmin(1.0, fmax(0.0, ramp));
    double invf = ramp / (32.0 * freq) + (1.0 - ramp) / freq;
    invf_out[i] = (float)invf;
}

// ---------------------------------------------------------------------------
// RoPE apply (pure fp32)
// ---------------------------------------------------------------------------
__global__ void rope_kernel(float* __restrict__ qkv,
                            const float* __restrict__ invf)
{
    const int t  = blockIdx.x;
    const int hh = blockIdx.y * blockDim.y + threadIdx.y;   // 0..71
    if (hh >= NH + NKV) return;
    const int i = threadIdx.x;                               // 0..31

    float ang = (float)t * __ldg(&invf[i]);
    const float conc = 0.1f * logf(32.0f) + 1.0f;
    float s, c;
    sincosf(ang, &s, &c);
    c *= conc; s *= conc;

    float* p = qkv + (size_t)t * QKV_DIM
             + (hh < NH ? hh * HD : QDIM + (hh - NH) * HD);
    float x1 = p[i], x2 = p[i + 32];
    p[i]      = x1 * c - x2 * s;
    p[i + 32] = x2 * c + x1 * s;
}

// ===========================================================================
// MMA attention: block = (token t, kv head), 128 threads (4 warps).
//   S^T[j=128][h=8] = K[j][d] @ Q[h][d]^T   (split-bf16, 3 terms, Q pre-scaled)
//   softmax per head (sink in denominator), P split bf16
//   O^T[d=64][h=8] = V^T[d][j] @ P^T[h][j]^T (split, 3 terms)
// smem pitches: K/V/Q rows 144 B (bank-staggered), S fp32 pitch 10,
// P rows 272 B, Osm fp32 pitch 9.
// ===========================================================================
#define AK_H 0
#define AK_L 18432
#define AV_H 36864
#define AV_L 55296
#define AQ_H 73728
#define AQ_L 74880
#define AS_F 76032
#define AP_H 81152
#define AP_L 83328
#define AO_F 85504
#define ATTN_SMEM 87808

__global__ void __launch_bounds__(128) attn_kernel(
    const float* __restrict__ qkv, const float* __restrict__ sinks,
    __nv_bfloat16* __restrict__ outh, __nv_bfloat16* __restrict__ outl)
{
    extern __shared__ char smc[];
    const uint32_t sb = smem_u32(smc);
    const int t   = blockIdx.x;
    const int hkv = blockIdx.y;
    const int j0  = max(0, t - (WIN - 1));
    const int cnt = t - j0 + 1;
    const int tid = threadIdx.x;
    const int warp = tid >> 5;
    const int lane = tid & 31;

    // ---- fill K/V (split bf16, zero pad rows >= cnt) ----
    for (int i = tid; i < WIN * 8; i += 128) {
        int j = i >> 3, c8 = i & 7;          // 8 d-values per chunk
        uint4 kh, kl, vh, vl;
        if (j < cnt) {
            const float* row = qkv + (size_t)(j0 + j) * QKV_DIM + QDIM + hkv * HD;
            float4 k0 = ((const float4*)row)[c8 * 2];
            float4 k1 = ((const float4*)row)[c8 * 2 + 1];
            float4 v0 = ((const float4*)(row + NKV * HD))[c8 * 2];
            float4 v1 = ((const float4*)(row + NKV * HD))[c8 * 2 + 1];
            split_pair(k0.x, k0.y, kh.x, kl.x);
            split_pair(k0.z, k0.w, kh.y, kl.y);
            split_pair(k1.x, k1.y, kh.z, kl.z);
            split_pair(k1.z, k1.w, kh.w, kl.w);
            split_pair(v0.x, v0.y, vh.x, vl.x);
            split_pair(v0.z, v0.w, vh.y, vl.y);
            split_pair(v1.x, v1.y, vh.z, vl.z);
            split_pair(v1.z, v1.w, vh.w, vl.w);
        } else {
            kh = kl = vh = vl = make_uint4(0, 0, 0, 0);
        }
        uint32_t off = (uint32_t)j * 144u + (uint32_t)c8 * 16u;
        *(uint4*)(smc + AK_H + off) = kh;
        *(uint4*)(smc + AK_L + off) = kl;
        *(uint4*)(smc + AV_H + off) = vh;
        *(uint4*)(smc + AV_L + off) = vl;
    }
    // ---- fill Q (scaled by SM_SCALE, split bf16) ----
    {
        int i = tid;                          // 128 threads = 8 heads x 16 chunks
        int h = i >> 4, c4 = i & 15;
        const float4* qp = (const float4*)(qkv + (size_t)t * QKV_DIM
                                           + (hkv * 8 + h) * HD);
        float4 q = qp[c4];
        q.x *= SM_SCALE; q.y *= SM_SCALE; q.z *= SM_SCALE; q.w *= SM_SCALE;
        uint32_t h0, l0, h1, l1;
        split_pair(q.x, q.y, h0, l0);
        split_pair(q.z, q.w, h1, l1);
        uint32_t off = (uint32_t)h * 144u + (uint32_t)c4 * 8u;
        *(uint2*)(smc + AQ_H + off) = make_uint2(h0, h1);
        *(uint2*)(smc + AQ_L + off) = make_uint2(l0, l1);
    }
    __syncthreads();

    // ---- QK: S^T[j][h], warp w handles j-mtiles {2w, 2w+1} ----
    {
        // B frags (Q): depend only on k-step
        uint32_t bh[4][2], bl[4][2];
        #pragma unroll
        for (int ks = 0; ks < 4; ks++) {
            uint32_t addr = sb + AQ_H + (uint32_t)(lane & 7) * 144u
                          + (uint32_t)ks * 32u + (uint32_t)((lane >> 3) & 1) * 16u;
            ldsm_x2(bh[ks], addr);
            ldsm_x2(bl[ks], addr + (AQ_L - AQ_H));
        }
        float* Sf = (float*)(smc + AS_F);
        #pragma unroll
        for (int mi = 0; mi < 2; mi++) {
            const int mt = warp * 2 + mi;
            float c[4] = {0.f, 0.f, 0.f, 0.f};
            #pragma unroll
            for (int ks = 0; ks < 4; ks++) {
                uint32_t ah[4], al[4];
                uint32_t addr = sb + AK_H
                              + (uint32_t)(mt * 16 + (lane & 15)) * 144u
                              + (uint32_t)ks * 32u + (uint32_t)(lane >> 4) * 16u;
                ldsm_x4(ah, addr);
                ldsm_x4(al, addr + (AK_L - AK_H));
                mma16816(c, ah, bh[ks]);
                mma16816(c, al, bh[ks]);
                mma16816(c, ah, bl[ks]);
            }
            int j  = mt * 16 + (lane >> 2);
            int hc = (lane & 3) * 2;
            *(float2*)&Sf[j * 10 + hc]       = make_float2(c[0], c[1]);
            *(float2*)&Sf[(j + 8) * 10 + hc] = make_float2(c[2], c[3]);
        }
    }
    __syncthreads();

    // ---- softmax per head; warp w handles heads 2w, 2w+1 ----
    {
        const float* Sf = (const float*)(smc + AS_F);
        __nv_bfloat16* Ph = (__nv_bfloat16*)(smc + AP_H);
        __nv_bfloat16* Pl = (__nv_bfloat16*)(smc + AP_L);
        #pragma unroll
        for (int hi = 0; hi < 2; hi++) {
            const int h = warp * 2 + hi;
            float s[4], m = -INFINITY;
            #pragma unroll
            for (int r = 0; r < 4; r++) {
                int j = lane + r * 32;
                s[r] = (j < cnt) ? Sf[j * 10 + h] : -INFINITY;
                m = fmaxf(m, s[r]);
            }
            #pragma unroll
            for (int o = 16; o; o >>= 1) m = fmaxf(m, __shfl_xor_sync(~0u, m, o));
            float sum = 0.f;
            #pragma unroll
            for (int r = 0; r < 4; r++) {
                float e = (s[r] == -INFINITY) ? 0.f : expf(s[r] - m);
                s[r] = e;
                sum += e;
            }
            #pragma unroll
            for (int o = 16; o; o >>= 1) sum += __shfl_xor_sync(~0u, sum, o);
            const float invd = 1.f / (sum + expf(sinks[hkv * 8 + h] - m));
            #pragma unroll
            for (int r = 0; r < 4; r++) {
                int j = lane + r * 32;
                float p = s[r] * invd;
                __nv_bfloat16 ph = __float2bfloat16(p);
                __nv_bfloat16 pl = __float2bfloat16(p - __bfloat162float(ph));
                Ph[h * 136 + j] = ph;
                Pl[h * 136 + j] = pl;
            }
        }
    }
    __syncthreads();

    // ---- PV: O^T[d][h], warp w handles d-mtile w ----
    {
        float c[4] = {0.f, 0.f, 0.f, 0.f};
        #pragma unroll
        for (int kt = 0; kt < 8; kt++) {
            uint32_t ah[4], al[4], bh[2], bl[2];
            // A = V^T tile (d = w*16.., j = kt*16..) via ldsm.x4.trans
            uint32_t jrow = (uint32_t)(kt * 16 + (lane & 7) + ((lane >> 4) & 1) * 8);
            uint32_t dcol = (uint32_t)(warp * 16 + ((lane >> 3) & 1) * 8);
            uint32_t va = sb + AV_H + jrow * 144u + dcol * 2u;
            ldsm_x4t(ah, va);
            ldsm_x4t(al, va + (AV_L - AV_H));
            // B = P^T rows h, k = j chunk
            uint32_t pa = sb + AP_H + (uint32_t)(lane & 7) * 272u
                        + (uint32_t)kt * 32u + (uint32_t)((lane >> 3) & 1) * 16u;
            ldsm_x2(bh, pa);
            ldsm_x2(bl, pa + (AP_L - AP_H));
            mma16816(c, ah, bh);
            mma16816(c, al, bh);
            mma16816(c, ah, bl);
        }
        float* Os = (float*)(smc + AO_F);
        int d  = warp * 16 + (lane >> 2);
        int hc = (lane & 3) * 2;
        Os[d * 9 + hc]           = c[0];
        Os[d * 9 + hc + 1]       = c[1];
        Os[(d + 8) * 9 + hc]     = c[2];
        Os[(d + 8) * 9 + hc + 1] = c[3];
    }
    __syncthreads();

    // ---- write output: split bf16, coalesced ----
    {
        const float* Os = (const float*)(smc + AO_F);
        int o = tid * 4;                    // 128 threads x 4 = 512
        int h = o >> 6, d0 = o & 63;
        float f0 = Os[(d0 + 0) * 9 + h];
        float f1 = Os[(d0 + 1) * 9 + h];
        float f2 = Os[(d0 + 2) * 9 + h];
        float f3 = Os[(d0 + 3) * 9 + h];
        uint32_t h0, l0, h1, l1;
        split_pair(f0, f1, h0, l0);
        split_pair(f2, f3, h1, l1);
        size_t base = (size_t)t * QDIM + hkv * 512 + o;
        *(uint2*)(outh + base) = make_uint2(h0, h1);
        *(uint2*)(outl + base) = make_uint2(l0, l1);
    }
}

// ---------------------------------------------------------------------------
extern "C" void kernel_launch(void* const* d_in, const int* in_sizes, int n_in,
                              void* d_out, int out_size)
{
    const float* x      = (const float*)d_in[0];
    const float* W_qkv  = (const float*)d_in[1];
    const float* b_qkv  = (const float*)d_in[2];
    const float* W_out  = (const float*)d_in[3];
    const float* b_out  = (const float*)d_in[4];
    const float* sinks  = (const float*)d_in[5];
    float* out = (float*)d_out;

    float *qkv_ptr, *invf_ptr;
    __nv_bfloat16 *xh, *xl, *wqh, *wql, *woh, *wol, *ath, *atl;
    cudaGetSymbolAddress((void**)&qkv_ptr, g_qkv);
    cudaGetSymbolAddress((void**)&invf_ptr, g_invf);
    cudaGetSymbolAddress((void**)&xh, g_xh);
    cudaGetSymbolAddress((void**)&xl, g_xl);
    cudaGetSymbolAddress((void**)&wqh, g_wqh);
    cudaGetSymbolAddress((void**)&wql, g_wql);
    cudaGetSymbolAddress((void**)&woh, g_woh);
    cudaGetSymbolAddress((void**)&wol, g_wol);
    cudaGetSymbolAddress((void**)&ath, g_ath);
    cudaGetSymbolAddress((void**)&atl, g_atl);

    cudaFuncSetAttribute(hmma_gemm_bias,
                         cudaFuncAttributeMaxDynamicSharedMemorySize,
                         GEMM_SMEM_BYTES);
    cudaFuncSetAttribute(attn_kernel, cudaFuncAttributeMaxDynamicSharedMemorySize,
                         ATTN_SMEM);

    // 0) rope table + split inputs to bf16 hi/lo
    rope_table_kernel<<<1, 32>>>(invf_ptr);
    {
        int n4 = T_SEQ * D_MODEL / 4;
        split_kernel<<<(n4 + 255) / 256, 256>>>(
            (const float4*)x, (uint2*)xh, (uint2*)xl, n4);
        n4 = D_MODEL * QKV_DIM / 4;
        split_kernel<<<(n4 + 255) / 256, 256>>>(
            (const float4*)W_qkv, (uint2*)wqh, (uint2*)wql, n4);
        n4 = QDIM * D_MODEL / 4;
        split_kernel<<<(n4 + 255) / 256, 256>>>(
            (const float4*)W_out, (uint2*)wol ? (uint2*)woh : nullptr, (uint2*)wol, n4);
    }

    // 1) qkv = x @ W_qkv + b_qkv          (1536 x 5120, K=2880)
    {
        dim3 grid(QKV_DIM / 128, T_SEQ / 128);
        hmma_gemm_bias<<<grid, 256, GEMM_SMEM_BYTES>>>(
            xh, xl, wqh, wql, b_qkv, qkv_ptr, T_SEQ, QKV_DIM, D_MODEL);
    }
    // 2) RoPE in place on q,k slices (fp32, table-based)
    {
        dim3 grid(T_SEQ, 9);
        dim3 block(32, 8);
        rope_kernel<<<grid, block>>>(qkv_ptr, invf_ptr);
    }
    // 3) sliding-window GQA attention with sinks -> split bf16 (MMA version)
    {
        dim3 grid(T_SEQ, NKV);
        attn_kernel<<<grid, 128, ATTN_SMEM>>>(qkv_ptr, sinks, ath, atl);
    }
    // 4) out = attn @ W_out + b_out       (1536 x 2880, K=4096)
    {
        dim3 grid((D_MODEL + 127) / 128, T_SEQ / 128);
        hmma_gemm_bias<<<grid, 256, GEMM_SMEM_BYTES>>>(
            ath, atl, woh, wol, b_out, out, T_SEQ, D_MODEL, QDIM);
    }
}

// round 12
// speedup vs baseline: 4.0222x; 1.0878x over previous
#include <cuda_runtime.h>
#include <cuda_bf16.h>
#include <math.h>
#include <cstdint>

// Problem dims (fixed by reference)
#define T_SEQ   1536
#define D_MODEL 2880
#define NH      64
#define NKV     8
#define HD      64
#define QKV_DIM 5120          // 64*(64+16)
#define QDIM    4096          // NH*HD
#define WIN     128
#define SM_SCALE 0.125f

// Scratch (allocation-free rule: device globals)
__device__ float g_qkv[T_SEQ * QKV_DIM];            // fp32 qkv (GEMM1 out)
__device__ float g_invf[32];                        // rope inv_freq table
// split-bf16 operands
__device__ __nv_bfloat16 g_xh[T_SEQ * D_MODEL];
__device__ __nv_bfloat16 g_xl[T_SEQ * D_MODEL];
__device__ __nv_bfloat16 g_wqh[D_MODEL * QKV_DIM];
__device__ __nv_bfloat16 g_wql[D_MODEL * QKV_DIM];
__device__ __nv_bfloat16 g_woh[QDIM * D_MODEL];
__device__ __nv_bfloat16 g_wol[QDIM * D_MODEL];
__device__ __nv_bfloat16 g_ath[T_SEQ * QDIM];       // attn out hi
__device__ __nv_bfloat16 g_atl[T_SEQ * QDIM];       // attn out lo
__device__ __nv_bfloat16 g_qh[T_SEQ * QKV_DIM];     // roped/scaled qkv hi
__device__ __nv_bfloat16 g_ql[T_SEQ * QKV_DIM];     // roped/scaled qkv lo

// ===========================================================================
// PTX helpers
// ===========================================================================
__device__ __forceinline__ uint32_t smem_u32(const void* p) {
    uint32_t a;
    asm("{ .reg .u64 t; cvta.to.shared.u64 t, %1; cvt.u32.u64 %0, t; }"
        : "=r"(a) : "l"(p));
    return a;
}
__device__ __forceinline__ void ldsm_x4(uint32_t r[4], uint32_t a) {
    asm volatile("ldmatrix.sync.aligned.m8n8.x4.shared.b16 {%0,%1,%2,%3}, [%4];"
        : "=r"(r[0]), "=r"(r[1]), "=r"(r[2]), "=r"(r[3]) : "r"(a));
}
__device__ __forceinline__ void ldsm_x4t(uint32_t r[4], uint32_t a) {
    asm volatile("ldmatrix.sync.aligned.m8n8.x4.trans.shared.b16 {%0,%1,%2,%3}, [%4];"
        : "=r"(r[0]), "=r"(r[1]), "=r"(r[2]), "=r"(r[3]) : "r"(a));
}
__device__ __forceinline__ void ldsm_x2(uint32_t r[2], uint32_t a) {
    asm volatile("ldmatrix.sync.aligned.m8n8.x2.shared.b16 {%0,%1}, [%2];"
        : "=r"(r[0]), "=r"(r[1]) : "r"(a));
}
__device__ __forceinline__ void ldsm_x2t(uint32_t r[2], uint32_t a) {
    asm volatile("ldmatrix.sync.aligned.m8n8.x2.trans.shared.b16 {%0,%1}, [%2];"
        : "=r"(r[0]), "=r"(r[1]) : "r"(a));
}
__device__ __forceinline__ void mma16816(float c[4], const uint32_t a[4],
                                         const uint32_t b[2]) {
    asm volatile(
        "mma.sync.aligned.m16n8k16.row.col.f32.bf16.bf16.f32 "
        "{%0,%1,%2,%3}, {%4,%5,%6,%7}, {%8,%9}, {%0,%1,%2,%3};"
        : "+f"(c[0]), "+f"(c[1]), "+f"(c[2]), "+f"(c[3])
        : "r"(a[0]), "r"(a[1]), "r"(a[2]), "r"(a[3]), "r"(b[0]), "r"(b[1]));
}
__device__ __forceinline__ void cp16(uint32_t saddr, const void* gaddr,
                                     uint32_t srcsize) {
    asm volatile("cp.async.ca.shared.global [%0], [%1], 16, %2;"
        :: "r"(saddr), "l"(gaddr), "r"(srcsize));
}
__device__ __forceinline__ void cp_commit() {
    asm volatile("cp.async.commit_group;" ::: "memory");
}
template <int N>
__device__ __forceinline__ void cp_wait() {
    asm volatile("cp.async.wait_group %0;" :: "n"(N) : "memory");
}
// split fp32 pair into (hi, lo) packed bf16x2
__device__ __forceinline__ void split_pair(float x, float y,
                                           uint32_t& hi, uint32_t& lo) {
    __nv_bfloat16 hx = __float2bfloat16(x);
    __nv_bfloat16 hy = __float2bfloat16(y);
    float rx = x - __bfloat162float(hx);
    float ry = y - __bfloat162float(hy);
    __nv_bfloat162 hp = __halves2bfloat162(hx, hy);
    __nv_bfloat162 lp = __floats2bfloat162_rn(rx, ry);
    hi = *reinterpret_cast<uint32_t*>(&hp);
    lo = *reinterpret_cast<uint32_t*>(&lp);
}

// ===========================================================================
// Split kernel: fp32 -> (hi, lo) bf16, vectorized.
// ===========================================================================
__global__ void __launch_bounds__(256) split_kernel(
    const float4* __restrict__ in, uint2* __restrict__ hi,
    uint2* __restrict__ lo, int n4)
{
    int i = blockIdx.x * 256 + threadIdx.x;
    if (i < n4) {
        float4 v = in[i];
        uint32_t h0, l0, h1, l1;
        split_pair(v.x, v.y, h0, l0);
        split_pair(v.z, v.w, h1, l1);
        hi[i] = make_uint2(h0, h1);
        lo[i] = make_uint2(l0, l1);
    }
}

// ===========================================================================
// Split-bf16 HMMA GEMM with bias (pre-split operands, cp.async pipeline)
// ===========================================================================
#define SA_HI_OFF 0
#define SA_LO_OFF 10240
#define SB_HI_OFF 20480
#define SB_LO_OFF 29184
#define BUF_STRIDE 37888
#define EP_PITCH  132
#define GEMM_SMEM_BYTES (2 * BUF_STRIDE)   // 75776 (epilogue 67584 aliases)

__global__ void __launch_bounds__(256) hmma_gemm_bias(
    const __nv_bfloat16* __restrict__ Ah, const __nv_bfloat16* __restrict__ Al,
    const __nv_bfloat16* __restrict__ Bh, const __nv_bfloat16* __restrict__ Bl,
    const float* __restrict__ bias, float* __restrict__ C,
    int M, int N, int K)
{
    extern __shared__ char smem[];
    const uint32_t sb = smem_u32(smem);
    const int tid = threadIdx.x, lane = tid & 31, wid = tid >> 5;
    const int wm = wid >> 2, wn = wid & 3;
    const int m0 = blockIdx.y * 128, n0 = blockIdx.x * 128;

    float acc[4][4][4];
    #pragma unroll
    for (int mi = 0; mi < 4; mi++)
        #pragma unroll
        for (int ni = 0; ni < 4; ni++)
            #pragma unroll
            for (int q = 0; q < 4; q++) acc[mi][ni][q] = 0.f;

    const int am  = tid >> 2;
    const int aks = (tid & 3);
    const int bk  = tid >> 4;
    const int bns = (tid & 15);

    auto issue_chunk = [&](int k0, int buf) {
        const uint32_t bb = sb + (uint32_t)buf * BUF_STRIDE;
        #pragma unroll
        for (int r = 0; r < 2; r++) {
            int m = am + r * 64;
            const __nv_bfloat16* ga = Ah + (size_t)(m0 + m) * K + k0 + aks * 8;
            const __nv_bfloat16* gl = Al + (size_t)(m0 + m) * K + k0 + aks * 8;
            uint32_t so = (uint32_t)m * 80u + (uint32_t)aks * 16u;
            cp16(bb + SA_HI_OFF + so, ga, 16);
            cp16(bb + SA_LO_OFF + so, gl, 16);
        }
        #pragma unroll
        for (int r = 0; r < 2; r++) {
            int k = bk + r * 16;
            int ncol = n0 + bns * 8;
            uint32_t sz = (ncol < N) ? 16u : 0u;
            const __nv_bfloat16* gb = Bh + (size_t)(k0 + k) * N + ncol;
            const __nv_bfloat16* gl = Bl + (size_t)(k0 + k) * N + ncol;
            uint32_t so = (uint32_t)k * 272u + (uint32_t)bns * 16u;
            cp16(bb + SB_HI_OFF + so, gb, sz);
            cp16(bb + SB_LO_OFF + so, gl, sz);
        }
        cp_commit();
    };

    const int nch = K >> 5;
    issue_chunk(0, 0);

    for (int ch = 0; ch < nch; ch++) {
        if (ch + 1 < nch) {
            issue_chunk((ch + 1) * 32, (ch + 1) & 1);
            cp_wait<1>();
        } else {
            cp_wait<0>();
        }
        __syncthreads();

        const uint32_t bufb = sb + (uint32_t)(ch & 1) * BUF_STRIDE;
        #pragma unroll
        for (int s = 0; s < 2; s++) {
            uint32_t ah[4][4], al[4][4], bh[4][2], bl[4][2];
            const uint32_t arow  = (uint32_t)(lane & 15);
            const uint32_t acolb = (uint32_t)(s * 32 + (lane >> 4) * 16);
            #pragma unroll
            for (int mi = 0; mi < 4; mi++) {
                uint32_t addr = bufb + SA_HI_OFF
                              + (uint32_t)(wm * 64 + mi * 16 + arow) * 80u + acolb;
                ldsm_x4(ah[mi], addr);
                ldsm_x4(al[mi], addr + (SA_LO_OFF - SA_HI_OFF));
            }
            const uint32_t brow = (uint32_t)(s * 16 + (lane & 15));
            #pragma unroll
            for (int ni = 0; ni < 4; ni++) {
                uint32_t addr = bufb + SB_HI_OFF + brow * 272u
                              + (uint32_t)(wn * 32 + ni * 8) * 2u;
                ldsm_x2t(bh[ni], addr);
                ldsm_x2t(bl[ni], addr + (SB_LO_OFF - SB_HI_OFF));
            }
            #pragma unroll
            for (int mi = 0; mi < 4; mi++)
                #pragma unroll
                for (int ni = 0; ni < 4; ni++) {
                    mma16816(acc[mi][ni], ah[mi], bh[ni]);
                    mma16816(acc[mi][ni], al[mi], bh[ni]);
                    mma16816(acc[mi][ni], ah[mi], bl[ni]);
                }
        }
        __syncthreads();
    }

    float* ep = (float*)smem;
    #pragma unroll
    for (int mi = 0; mi < 4; mi++) {
        int r0 = wm * 64 + mi * 16 + (lane >> 2);
        #pragma unroll
        for (int ni = 0; ni < 4; ni++) {
            int c = wn * 32 + ni * 8 + (lane & 3) * 2;
            ep[r0 * EP_PITCH + c]           = acc[mi][ni][0];
            ep[r0 * EP_PITCH + c + 1]       = acc[mi][ni][1];
            ep[(r0 + 8) * EP_PITCH + c]     = acc[mi][ni][2];
            ep[(r0 + 8) * EP_PITCH + c + 1] = acc[mi][ni][3];
        }
    }
    __syncthreads();
    for (int i = tid; i < 4096; i += 256) {
        int r = i >> 5, cq = (i & 31) * 4;
        int col = n0 + cq;
        if (col < N) {
            float4 b4 = *(const float4*)(bias + col);
            float4 o;
            o.x = ep[r * EP_PITCH + cq + 0] + b4.x;
            o.y = ep[r * EP_PITCH + cq + 1] + b4.y;
            o.z = ep[r * EP_PITCH + cq + 2] + b4.z;
            o.w = ep[r * EP_PITCH + cq + 3] + b4.w;
            *(float4*)(C + (size_t)(m0 + r) * N + col) = o;
        }
    }
}

// ---------------------------------------------------------------------------
// RoPE inv_freq table init (32 threads, double precision, once per launch)
// ---------------------------------------------------------------------------
__global__ void rope_table_kernel(float* __restrict__ invf_out)
{
    const int i = threadIdx.x;   // 0..31
    const double lgbase = log(150000.0);
    const double low  = 32.0 * log(1024.0 / (32.0 * 2.0 * M_PI)) / lgbase;
    const double high = 32.0 * log(1024.0 / ( 1.0 * 2.0 * M_PI)) / lgbase;
    double freq = pow(150000.0, (double)(2 * i) / 64.0);
    double ramp = ((double)i - low) / (high - low);
    ramp = fmin(1.0, fmax(0.0, ramp));
    double invf = ramp / (32.0 * freq) + (1.0 - ramp) / freq;
    invf_out[i] = (float)invf;
}

// ===========================================================================
// Fused RoPE + scale + split: reads fp32 qkv, applies rope to q/k (fp32),
// scales q by SM_SCALE, writes split-bf16 hi/lo of the whole qkv row.
// One block per token, 256 threads.
// ===========================================================================
__global__ void __launch_bounds__(256) rope_split_qkv(
    const float* __restrict__ qkv, const float* __restrict__ invf,
    __nv_bfloat16* __restrict__ qh, __nv_bfloat16* __restrict__ ql)
{
    __shared__ float sinv[32];
    const int t = blockIdx.x;
    const int tid = threadIdx.x;
    if (tid < 32) sinv[tid] = invf[tid];
    __syncthreads();

    const float conc = 0.1f * logf(32.0f) + 1.0f;
    const float* row = qkv + (size_t)t * QKV_DIM;
    uint2* oh = (uint2*)(qh + (size_t)t * QKV_DIM);
    uint2* ol = (uint2*)(ql + (size_t)t * QKV_DIM);

    // roped heads: 72 heads x 8 pair-chunks (chunk c pairs floats 4c..4c+3
    // with 4c+32..4c+35 within the head)
    for (int i = tid; i < (NH + NKV) * 8; i += 256) {
        int hh = i >> 3, c = i & 7;
        int base = (hh < NH) ? hh * HD : QDIM + (hh - NH) * HD;
        const float4 a = ((const float4*)(row + base))[c];
        const float4 b = ((const float4*)(row + base))[c + 8];
        float na[4], nb[4];
        const float av[4] = {a.x, a.y, a.z, a.w};
        const float bv[4] = {b.x, b.y, b.z, b.w};
        #pragma unroll
        for (int q = 0; q < 4; q++) {
            float ang = (float)t * sinv[c * 4 + q];
            float s, cc;
            sincosf(ang, &s, &cc);
            cc *= conc; s *= conc;
            na[q] = av[q] * cc - bv[q] * s;
            nb[q] = bv[q] * cc + av[q] * s;
        }
        if (hh < NH) {
            #pragma unroll
            for (int q = 0; q < 4; q++) { na[q] *= SM_SCALE; nb[q] *= SM_SCALE; }
        }
        uint32_t h0, l0, h1, l1;
        split_pair(na[0], na[1], h0, l0);
        split_pair(na[2], na[3], h1, l1);
        oh[base / 4 + c] = make_uint2(h0, h1);
        ol[base / 4 + c] = make_uint2(l0, l1);
        split_pair(nb[0], nb[1], h0, l0);
        split_pair(nb[2], nb[3], h1, l1);
        oh[base / 4 + c + 8] = make_uint2(h0, h1);
        ol[base / 4 + c + 8] = make_uint2(l0, l1);
    }
    // v region: plain split (512 floats = 128 float4)
    const int vbase4 = (QDIM + NKV * HD) / 4;
    for (int i = tid; i < 128; i += 256) {
        float4 v = ((const float4*)row)[vbase4 + i];
        uint32_t h0, l0, h1, l1;
        split_pair(v.x, v.y, h0, l0);
        split_pair(v.z, v.w, h1, l1);
        oh[vbase4 + i] = make_uint2(h0, h1);
        ol[vbase4 + i] = make_uint2(l0, l1);
    }
}

// ===========================================================================
// MMA attention: block = (token t, kv head), 128 threads (4 warps).
// Fill = cp.async copies from pre-split arrays (zero conversion math).
// ===========================================================================
#define AK_H 0
#define AK_L 18432
#define AV_H 36864
#define AV_L 55296
#define AQ_H 73728
#define AQ_L 74880
#define AS_F 76032
#define AP_H 81152
#define AP_L 83328
#define AO_F 85504
#define ATTN_SMEM 87808

__global__ void __launch_bounds__(128) attn_kernel(
    const __nv_bfloat16* __restrict__ qh, const __nv_bfloat16* __restrict__ ql,
    const float* __restrict__ sinks,
    __nv_bfloat16* __restrict__ outh, __nv_bfloat16* __restrict__ outl)
{
    extern __shared__ char smc[];
    const uint32_t sb = smem_u32(smc);
    const int t   = blockIdx.x;
    const int hkv = blockIdx.y;
    const int j0  = max(0, t - (WIN - 1));
    const int cnt = t - j0 + 1;
    const int tid = threadIdx.x;
    const int warp = tid >> 5;
    const int lane = tid & 31;

    // ---- fill K/V via cp.async (src_size=0 zero-fills pad rows) ----
    const size_t koff = QDIM + (size_t)hkv * HD;
    const size_t voff = QDIM + NKV * HD + (size_t)hkv * HD;
    for (int i = tid; i < WIN * 8; i += 128) {
        int j = i >> 3, c8 = i & 7;
        int jc = min(j, cnt - 1);
        uint32_t sz = (j < cnt) ? 16u : 0u;
        size_t rowk = (size_t)(j0 + jc) * QKV_DIM + koff + c8 * 8;
        size_t rowv = (size_t)(j0 + jc) * QKV_DIM + voff + c8 * 8;
        uint32_t off = (uint32_t)j * 144u + (uint32_t)c8 * 16u;
        cp16(sb + AK_H + off, qh + rowk, sz);
        cp16(sb + AK_L + off, ql + rowk, sz);
        cp16(sb + AV_H + off, qh + rowv, sz);
        cp16(sb + AV_L + off, ql + rowv, sz);
    }
    // ---- fill Q (pre-scaled, pre-roped, pre-split) ----
    {
        int i = tid;                 // 128 = 2 arrays x 8 heads x 8 chunks
        int hilo = i >> 6, h = (i >> 3) & 7, c8 = i & 7;
        size_t src = (size_t)t * QKV_DIM + (hkv * 8 + h) * HD + c8 * 8;
        uint32_t off = (uint32_t)h * 144u + (uint32_t)c8 * 16u;
        if (hilo == 0) cp16(sb + AQ_H + off, qh + src, 16);
        else           cp16(sb + AQ_L + off, ql + src, 16);
    }
    cp_commit();
    cp_wait<0>();
    __syncthreads();

    // ---- QK: S^T[j][h], warp w handles j-mtiles {2w, 2w+1} ----
    {
        uint32_t bh[4][2], bl[4][2];
        #pragma unroll
        for (int ks = 0; ks < 4; ks++) {
            uint32_t addr = sb + AQ_H + (uint32_t)(lane & 7) * 144u
                          + (uint32_t)ks * 32u + (uint32_t)((lane >> 3) & 1) * 16u;
            ldsm_x2(bh[ks], addr);
            ldsm_x2(bl[ks], addr + (AQ_L - AQ_H));
        }
        float* Sf = (float*)(smc + AS_F);
        #pragma unroll
        for (int mi = 0; mi < 2; mi++) {
            const int mt = warp * 2 + mi;
            float c[4] = {0.f, 0.f, 0.f, 0.f};
            #pragma unroll
            for (int ks = 0; ks < 4; ks++) {
                uint32_t ah[4], al[4];
                uint32_t addr = sb + AK_H
                              + (uint32_t)(mt * 16 + (lane & 15)) * 144u
                              + (uint32_t)ks * 32u + (uint32_t)(lane >> 4) * 16u;
                ldsm_x4(ah, addr);
                ldsm_x4(al, addr + (AK_L - AK_H));
                mma16816(c, ah, bh[ks]);
                mma16816(c, al, bh[ks]);
                mma16816(c, ah, bl[ks]);
            }
            int j  = mt * 16 + (lane >> 2);
            int hc = (lane & 3) * 2;
            *(float2*)&Sf[j * 10 + hc]       = make_float2(c[0], c[1]);
            *(float2*)&Sf[(j + 8) * 10 + hc] = make_float2(c[2], c[3]);
        }
    }
    __syncthreads();

    // ---- softmax per head; warp w handles heads 2w, 2w+1 ----
    {
        const float* Sf = (const float*)(smc + AS_F);
        __nv_bfloat16* Ph = (__nv_bfloat16*)(smc + AP_H);
        __nv_bfloat16* Pl = (__nv_bfloat16*)(smc + AP_L);
        #pragma unroll
        for (int hi = 0; hi < 2; hi++) {
            const int h = warp * 2 + hi;
            float s[4], m = -INFINITY;
            #pragma unroll
            for (int r = 0; r < 4; r++) {
                int j = lane + r * 32;
                s[r] = (j < cnt) ? Sf[j * 10 + h] : -INFINITY;
                m = fmaxf(m, s[r]);
            }
            #pragma unroll
            for (int o = 16; o; o >>= 1) m = fmaxf(m, __shfl_xor_sync(~0u, m, o));
            float sum = 0.f;
            #pragma unroll
            for (int r = 0; r < 4; r++) {
                float e = (s[r] == -INFINITY) ? 0.f : expf(s[r] - m);
                s[r] = e;
                sum += e;
            }
            #pragma unroll
            for (int o = 16; o; o >>= 1) sum += __shfl_xor_sync(~0u, sum, o);
            const float invd = 1.f / (sum + expf(sinks[hkv * 8 + h] - m));
            #pragma unroll
            for (int r = 0; r < 4; r++) {
                int j = lane + r * 32;
                float p = s[r] * invd;
                __nv_bfloat16 ph = __float2bfloat16(p);
                __nv_bfloat16 pl = __float2bfloat16(p - __bfloat162float(ph));
                Ph[h * 136 + j] = ph;
                Pl[h * 136 + j] = pl;
            }
        }
    }
    __syncthreads();

    // ---- PV: O^T[d][h], warp w handles d-mtile w ----
    {
        float c[4] = {0.f, 0.f, 0.f, 0.f};
        #pragma unroll
        for (int kt = 0; kt < 8; kt++) {
            uint32_t ah[4], al[4], bh[2], bl[2];
            uint32_t jrow = (uint32_t)(kt * 16 + (lane & 7) + ((lane >> 4) & 1) * 8);
            uint32_t dcol = (uint32_t)(warp * 16 + ((lane >> 3) & 1) * 8);
            uint32_t va = sb + AV_H + jrow * 144u + dcol * 2u;
            ldsm_x4t(ah, va);
            ldsm_x4t(al, va + (AV_L - AV_H));
            uint32_t pa = sb + AP_H + (uint32_t)(lane & 7) * 272u
                        + (uint32_t)kt * 32u + (uint32_t)((lane >> 3) & 1) * 16u;
            ldsm_x2(bh, pa);
            ldsm_x2(bl, pa + (AP_L - AP_H));
            mma16816(c, ah, bh);
            mma16816(c, al, bh);
            mma16816(c, ah, bl);
        }
        float* Os = (float*)(smc + AO_F);
        int d  = warp * 16 + (lane >> 2);
        int hc = (lane & 3) * 2;
        Os[d * 9 + hc]           = c[0];
        Os[d * 9 + hc + 1]       = c[1];
        Os[(d + 8) * 9 + hc]     = c[2];
        Os[(d + 8) * 9 + hc + 1] = c[3];
    }
    __syncthreads();

    // ---- write output: split bf16, coalesced ----
    {
        const float* Os = (const float*)(smc + AO_F);
        int o = tid * 4;
        int h = o >> 6, d0 = o & 63;
        float f0 = Os[(d0 + 0) * 9 + h];
        float f1 = Os[(d0 + 1) * 9 + h];
        float f2 = Os[(d0 + 2) * 9 + h];
        float f3 = Os[(d0 + 3) * 9 + h];
        uint32_t h0, l0, h1, l1;
        split_pair(f0, f1, h0, l0);
        split_pair(f2, f3, h1, l1);
        size_t base = (size_t)t * QDIM + hkv * 512 + o;
        *(uint2*)(outh + base) = make_uint2(h0, h1);
        *(uint2*)(outl + base) = make_uint2(l0, l1);
    }
}

// ---------------------------------------------------------------------------
extern "C" void kernel_launch(void* const* d_in, const int* in_sizes, int n_in,
                              void* d_out, int out_size)
{
    const float* x      = (const float*)d_in[0];
    const float* W_qkv  = (const float*)d_in[1];
    const float* b_qkv  = (const float*)d_in[2];
    const float* W_out  = (const float*)d_in[3];
    const float* b_out  = (const float*)d_in[4];
    const float* sinks  = (const float*)d_in[5];
    float* out = (float*)d_out;

    float *qkv_ptr, *invf_ptr;
    __nv_bfloat16 *xh, *xl, *wqh, *wql, *woh, *wol, *ath, *atl, *qh, *ql;
    cudaGetSymbolAddress((void**)&qkv_ptr, g_qkv);
    cudaGetSymbolAddress((void**)&invf_ptr, g_invf);
    cudaGetSymbolAddress((void**)&xh, g_xh);
    cudaGetSymbolAddress((void**)&xl, g_xl);
    cudaGetSymbolAddress((void**)&wqh, g_wqh);
    cudaGetSymbolAddress((void**)&wql, g_wql);
    cudaGetSymbolAddress((void**)&woh, g_woh);
    cudaGetSymbolAddress((void**)&wol, g_wol);
    cudaGetSymbolAddress((void**)&ath, g_ath);
    cudaGetSymbolAddress((void**)&atl, g_atl);
    cudaGetSymbolAddress((void**)&qh, g_qh);
    cudaGetSymbolAddress((void**)&ql, g_ql);

    cudaFuncSetAttribute(hmma_gemm_bias,
                         cudaFuncAttributeMaxDynamicSharedMemorySize,
                         GEMM_SMEM_BYTES);
    cudaFuncSetAttribute(attn_kernel, cudaFuncAttributeMaxDynamicSharedMemorySize,
                         ATTN_SMEM);

    // 0) rope table + split inputs to bf16 hi/lo
    rope_table_kernel<<<1, 32>>>(invf_ptr);
    {
        int n4 = T_SEQ * D_MODEL / 4;
        split_kernel<<<(n4 + 255) / 256, 256>>>(
            (const float4*)x, (uint2*)xh, (uint2*)xl, n4);
        n4 = D_MODEL * QKV_DIM / 4;
        split_kernel<<<(n4 + 255) / 256, 256>>>(
            (const float4*)W_qkv, (uint2*)wqh, (uint2*)wql, n4);
        n4 = QDIM * D_MODEL / 4;
        split_kernel<<<(n4 + 255) / 256, 256>>>(
            (const float4*)W_out, (uint2*)woh, (uint2*)wol, n4);
    }

    // 1) qkv = x @ W_qkv + b_qkv          (1536 x 5120, K=2880)
    {
        dim3 grid(QKV_DIM / 128, T_SEQ / 128);
        hmma_gemm_bias<<<grid, 256, GEMM_SMEM_BYTES>>>(
            xh, xl, wqh, wql, b_qkv, qkv_ptr, T_SEQ, QKV_DIM, D_MODEL);
    }
    // 2) fused rope + scale + split -> g_qh / g_ql
    rope_split_qkv<<<T_SEQ, 256>>>(qkv_ptr, invf_ptr, qh, ql);

    // 3) sliding-window GQA attention with sinks -> split bf16
    {
        dim3 grid(T_SEQ, NKV);
        attn_kernel<<<grid, 128, ATTN_SMEM>>>(qh, ql, sinks, ath, atl);
    }
    // 4) out = attn @ W_out + b_out       (1536 x 2880, K=4096)
    {
        dim3 grid((D_MODEL + 127) / 128, T_SEQ / 128);
        hmma_gemm_bias<<<grid, 256, GEMM_SMEM_BYTES>>>(
            ath, atl, woh, wol, b_out, out, T_SEQ, D_MODEL, QDIM);
    }
}

// round 14
// speedup vs baseline: 4.7767x; 1.1876x over previous
#include <cuda_runtime.h>
#include <cuda_bf16.h>
#include <math.h>
#include <cstdint>

// Problem dims (fixed by reference)
#define T_SEQ   1536
#define D_MODEL 2880
#define NH      64
#define NKV     8
#define HD      64
#define QKV_DIM 5120          // 64*(64+16)
#define QDIM    4096          // NH*HD
#define WIN     128
#define SM_SCALE 0.125f

// Scratch (allocation-free rule: device globals)
__device__ float g_qkv[T_SEQ * QKV_DIM];            // fp32 qkv (GEMM1 out)
__device__ float g_invf[32];                        // rope inv_freq table
// split-bf16 operands
__device__ __nv_bfloat16 g_xh[T_SEQ * D_MODEL];
__device__ __nv_bfloat16 g_xl[T_SEQ * D_MODEL];
__device__ __nv_bfloat16 g_wqh[D_MODEL * QKV_DIM];
__device__ __nv_bfloat16 g_wql[D_MODEL * QKV_DIM];
__device__ __nv_bfloat16 g_woh[QDIM * D_MODEL];
__device__ __nv_bfloat16 g_wol[QDIM * D_MODEL];
__device__ __nv_bfloat16 g_ath[T_SEQ * QDIM];       // attn out hi
__device__ __nv_bfloat16 g_atl[T_SEQ * QDIM];       // attn out lo
__device__ __nv_bfloat16 g_qh[T_SEQ * QKV_DIM];     // roped/scaled qkv hi
__device__ __nv_bfloat16 g_ql[T_SEQ * QKV_DIM];     // roped/scaled qkv lo

// ===========================================================================
// PTX helpers
// ===========================================================================
__device__ __forceinline__ uint32_t smem_u32(const void* p) {
    uint32_t a;
    asm("{ .reg .u64 t; cvta.to.shared.u64 t, %1; cvt.u32.u64 %0, t; }"
        : "=r"(a) : "l"(p));
    return a;
}
__device__ __forceinline__ void ldsm_x4(uint32_t r[4], uint32_t a) {
    asm volatile("ldmatrix.sync.aligned.m8n8.x4.shared.b16 {%0,%1,%2,%3}, [%4];"
        : "=r"(r[0]), "=r"(r[1]), "=r"(r[2]), "=r"(r[3]) : "r"(a));
}
__device__ __forceinline__ void ldsm_x4t(uint32_t r[4], uint32_t a) {
    asm volatile("ldmatrix.sync.aligned.m8n8.x4.trans.shared.b16 {%0,%1,%2,%3}, [%4];"
        : "=r"(r[0]), "=r"(r[1]), "=r"(r[2]), "=r"(r[3]) : "r"(a));
}
__device__ __forceinline__ void ldsm_x2(uint32_t r[2], uint32_t a) {
    asm volatile("ldmatrix.sync.aligned.m8n8.x2.shared.b16 {%0,%1}, [%2];"
        : "=r"(r[0]), "=r"(r[1]) : "r"(a));
}
__device__ __forceinline__ void mma16816(float c[4], const uint32_t a[4],
                                         const uint32_t b[2]) {
    asm volatile(
        "mma.sync.aligned.m16n8k16.row.col.f32.bf16.bf16.f32 "
        "{%0,%1,%2,%3}, {%4,%5,%6,%7}, {%8,%9}, {%0,%1,%2,%3};"
        : "+f"(c[0]), "+f"(c[1]), "+f"(c[2]), "+f"(c[3])
        : "r"(a[0]), "r"(a[1]), "r"(a[2]), "r"(a[3]), "r"(b[0]), "r"(b[1]));
}
__device__ __forceinline__ void cp16(uint32_t saddr, const void* gaddr,
                                     uint32_t srcsize) {
    asm volatile("cp.async.ca.shared.global [%0], [%1], 16, %2;"
        :: "r"(saddr), "l"(gaddr), "r"(srcsize));
}
__device__ __forceinline__ void cp_commit() {
    asm volatile("cp.async.commit_group;" ::: "memory");
}
template <int N>
__device__ __forceinline__ void cp_wait() {
    asm volatile("cp.async.wait_group %0;" :: "n"(N) : "memory");
}
// split fp32 pair into (hi, lo) packed bf16x2
__device__ __forceinline__ void split_pair(float x, float y,
                                           uint32_t& hi, uint32_t& lo) {
    __nv_bfloat16 hx = __float2bfloat16(x);
    __nv_bfloat16 hy = __float2bfloat16(y);
    float rx = x - __bfloat162float(hx);
    float ry = y - __bfloat162float(hy);
    __nv_bfloat162 hp = __halves2bfloat162(hx, hy);
    __nv_bfloat162 lp = __floats2bfloat162_rn(rx, ry);
    hi = *reinterpret_cast<uint32_t*>(&hp);
    lo = *reinterpret_cast<uint32_t*>(&lp);
}

// ===========================================================================
// Split kernel: fp32 -> (hi, lo) bf16, vectorized.
// ===========================================================================
__global__ void __launch_bounds__(256) split_kernel(
    const float4* __restrict__ in, uint2* __restrict__ hi,
    uint2* __restrict__ lo, int n4)
{
    int i = blockIdx.x * 256 + threadIdx.x;
    if (i < n4) {
        float4 v = in[i];
        uint32_t h0, l0, h1, l1;
        split_pair(v.x, v.y, h0, l0);
        split_pair(v.z, v.w, h1, l1);
        hi[i] = make_uint2(h0, h1);
        lo[i] = make_uint2(l0, l1);
    }
}

// ===========================================================================
// Split-bf16 HMMA GEMM with bias (pre-split operands, cp.async pipeline)
// 2 CTAs/SM via launch_bounds; B frags via ldsm.x4.trans (2 n-tiles/op).
// ===========================================================================
#define SA_HI_OFF 0
#define SA_LO_OFF 10240
#define SB_HI_OFF 20480
#define SB_LO_OFF 29184
#define BUF_STRIDE 37888
#define EP_PITCH  132
#define GEMM_SMEM_BYTES (2 * BUF_STRIDE)   // 75776 (epilogue 67584 aliases)

__global__ void __launch_bounds__(256, 2) hmma_gemm_bias(
    const __nv_bfloat16* __restrict__ Ah, const __nv_bfloat16* __restrict__ Al,
    const __nv_bfloat16* __restrict__ Bh, const __nv_bfloat16* __restrict__ Bl,
    const float* __restrict__ bias, float* __restrict__ C,
    int M, int N, int K)
{
    extern __shared__ char smem[];
    const uint32_t sb = smem_u32(smem);
    const int tid = threadIdx.x, lane = tid & 31, wid = tid >> 5;
    const int wm = wid >> 2, wn = wid & 3;
    const int m0 = blockIdx.y * 128, n0 = blockIdx.x * 128;

    float acc[4][4][4];
    #pragma unroll
    for (int mi = 0; mi < 4; mi++)
        #pragma unroll
        for (int ni = 0; ni < 4; ni++)
            #pragma unroll
            for (int q = 0; q < 4; q++) acc[mi][ni][q] = 0.f;

    const int am  = tid >> 2;
    const int aks = (tid & 3);
    const int bk  = tid >> 4;
    const int bns = (tid & 15);

    auto issue_chunk = [&](int k0, int buf) {
        const uint32_t bb = sb + (uint32_t)buf * BUF_STRIDE;
        #pragma unroll
        for (int r = 0; r < 2; r++) {
            int m = am + r * 64;
            const __nv_bfloat16* ga = Ah + (size_t)(m0 + m) * K + k0 + aks * 8;
            const __nv_bfloat16* gl = Al + (size_t)(m0 + m) * K + k0 + aks * 8;
            uint32_t so = (uint32_t)m * 80u + (uint32_t)aks * 16u;
            cp16(bb + SA_HI_OFF + so, ga, 16);
            cp16(bb + SA_LO_OFF + so, gl, 16);
        }
        #pragma unroll
        for (int r = 0; r < 2; r++) {
            int k = bk + r * 16;
            int ncol = n0 + bns * 8;
            uint32_t sz = (ncol < N) ? 16u : 0u;
            const __nv_bfloat16* gb = Bh + (size_t)(k0 + k) * N + ncol;
            const __nv_bfloat16* gl = Bl + (size_t)(k0 + k) * N + ncol;
            uint32_t so = (uint32_t)k * 272u + (uint32_t)bns * 16u;
            cp16(bb + SB_HI_OFF + so, gb, sz);
            cp16(bb + SB_LO_OFF + so, gl, sz);
        }
        cp_commit();
    };

    const int nch = K >> 5;
    issue_chunk(0, 0);

    for (int ch = 0; ch < nch; ch++) {
        if (ch + 1 < nch) {
            issue_chunk((ch + 1) * 32, (ch + 1) & 1);
            cp_wait<1>();
        } else {
            cp_wait<0>();
        }
        __syncthreads();

        const uint32_t bufb = sb + (uint32_t)(ch & 1) * BUF_STRIDE;
        #pragma unroll
        for (int s = 0; s < 2; s++) {
            uint32_t ah[4][4], al[4][4], bh[4][2], bl[4][2];
            const uint32_t arow  = (uint32_t)(lane & 15);
            const uint32_t acolb = (uint32_t)(s * 32 + (lane >> 4) * 16);
            #pragma unroll
            for (int mi = 0; mi < 4; mi++) {
                uint32_t addr = bufb + SA_HI_OFF
                              + (uint32_t)(wm * 64 + mi * 16 + arow) * 80u + acolb;
                ldsm_x4(ah[mi], addr);
                ldsm_x4(al[mi], addr + (SA_LO_OFF - SA_HI_OFF));
            }
            // B: one ldsm.x4.trans covers two adjacent n-tiles (k16 x n16)
            const uint32_t brow = (uint32_t)(s * 16 + (lane & 15));
            #pragma unroll
            for (int pr = 0; pr < 2; pr++) {
                uint32_t bt[4], btl[4];
                uint32_t addr = bufb + SB_HI_OFF + brow * 272u
                              + (uint32_t)(wn * 32 + pr * 16
                                           + ((lane >> 4) & 1) * 8) * 2u;
                ldsm_x4t(bt, addr);
                ldsm_x4t(btl, addr + (SB_LO_OFF - SB_HI_OFF));
                bh[pr * 2][0]     = bt[0];  bh[pr * 2][1]     = bt[1];
                bh[pr * 2 + 1][0] = bt[2];  bh[pr * 2 + 1][1] = bt[3];
                bl[pr * 2][0]     = btl[0]; bl[pr * 2][1]     = btl[1];
                bl[pr * 2 + 1][0] = btl[2]; bl[pr * 2 + 1][1] = btl[3];
            }
            #pragma unroll
            for (int mi = 0; mi < 4; mi++)
                #pragma unroll
                for (int ni = 0; ni < 4; ni++) {
                    mma16816(acc[mi][ni], ah[mi], bh[ni]);
                    mma16816(acc[mi][ni], al[mi], bh[ni]);
                    mma16816(acc[mi][ni], ah[mi], bl[ni]);
                }
        }
        __syncthreads();
    }

    float* ep = (float*)smem;
    #pragma unroll
    for (int mi = 0; mi < 4; mi++) {
        int r0 = wm * 64 + mi * 16 + (lane >> 2);
        #pragma unroll
        for (int ni = 0; ni < 4; ni++) {
            int c = wn * 32 + ni * 8 + (lane & 3) * 2;
            ep[r0 * EP_PITCH + c]           = acc[mi][ni][0];
            ep[r0 * EP_PITCH + c + 1]       = acc[mi][ni][1];
            ep[(r0 + 8) * EP_PITCH + c]     = acc[mi][ni][2];
            ep[(r0 + 8) * EP_PITCH + c + 1] = acc[mi][ni][3];
        }
    }
    __syncthreads();
    for (int i = tid; i < 4096; i += 256) {
        int r = i >> 5, cq = (i & 31) * 4;
        int col = n0 + cq;
        if (col < N) {
            float4 b4 = *(const float4*)(bias + col);
            float4 o;
            o.x = ep[r * EP_PITCH + cq + 0] + b4.x;
            o.y = ep[r * EP_PITCH + cq + 1] + b4.y;
            o.z = ep[r * EP_PITCH + cq + 2] + b4.z;
            o.w = ep[r * EP_PITCH + cq + 3] + b4.w;
            *(float4*)(C + (size_t)(m0 + r) * N + col) = o;
        }
    }
}

// ---------------------------------------------------------------------------
// RoPE inv_freq table init (32 threads, double precision, once per launch)
// ---------------------------------------------------------------------------
__global__ void rope_table_kernel(float* __restrict__ invf_out)
{
    const int i = threadIdx.x;   // 0..31
    const double lgbase = log(150000.0);
    const double low  = 32.0 * log(1024.0 / (32.0 * 2.0 * M_PI)) / lgbase;
    const double high = 32.0 * log(1024.0 / ( 1.0 * 2.0 * M_PI)) / lgbase;
    double freq = pow(150000.0, (double)(2 * i) / 64.0);
    double ramp = ((double)i - low) / (high - low);
    ramp = fmin(1.0, fmax(0.0, ramp));
    double invf = ramp / (32.0 * freq) + (1.0 - ramp) / freq;
    invf_out[i] = (float)invf;
}

// ===========================================================================
// Fused RoPE + scale + split (one block per token, 256 threads)
// ===========================================================================
__global__ void __launch_bounds__(256) rope_split_qkv(
    const float* __restrict__ qkv, const float* __restrict__ invf,
    __nv_bfloat16* __restrict__ qh, __nv_bfloat16* __restrict__ ql)
{
    __shared__ float sinv[32];
    const int t = blockIdx.x;
    const int tid = threadIdx.x;
    if (tid < 32) sinv[tid] = invf[tid];
    __syncthreads();

    const float conc = 0.1f * logf(32.0f) + 1.0f;
    const float* row = qkv + (size_t)t * QKV_DIM;
    uint2* oh = (uint2*)(qh + (size_t)t * QKV_DIM);
    uint2* ol = (uint2*)(ql + (size_t)t * QKV_DIM);

    for (int i = tid; i < (NH + NKV) * 8; i += 256) {
        int hh = i >> 3, c = i & 7;
        int base = (hh < NH) ? hh * HD : QDIM + (hh - NH) * HD;
        const float4 a = ((const float4*)(row + base))[c];
        const float4 b = ((const float4*)(row + base))[c + 8];
        float na[4], nb[4];
        const float av[4] = {a.x, a.y, a.z, a.w};
        const float bv[4] = {b.x, b.y, b.z, b.w};
        #pragma unroll
        for (int q = 0; q < 4; q++) {
            float ang = (float)t * sinv[c * 4 + q];
            float s, cc;
            sincosf(ang, &s, &cc);
            cc *= conc; s *= conc;
            na[q] = av[q] * cc - bv[q] * s;
            nb[q] = bv[q] * cc + av[q] * s;
        }
        if (hh < NH) {
            #pragma unroll
            for (int q = 0; q < 4; q++) { na[q] *= SM_SCALE; nb[q] *= SM_SCALE; }
        }
        uint32_t h0, l0, h1, l1;
        split_pair(na[0], na[1], h0, l0);
        split_pair(na[2], na[3], h1, l1);
        oh[base / 4 + c] = make_uint2(h0, h1);
        ol[base / 4 + c] = make_uint2(l0, l1);
        split_pair(nb[0], nb[1], h0, l0);
        split_pair(nb[2], nb[3], h1, l1);
        oh[base / 4 + c + 8] = make_uint2(h0, h1);
        ol[base / 4 + c + 8] = make_uint2(l0, l1);
    }
    const int vbase4 = (QDIM + NKV * HD) / 4;
    for (int i = tid; i < 128; i += 256) {
        float4 v = ((const float4*)row)[vbase4 + i];
        uint32_t h0, l0, h1, l1;
        split_pair(v.x, v.y, h0, l0);
        split_pair(v.z, v.w, h1, l1);
        oh[vbase4 + i] = make_uint2(h0, h1);
        ol[vbase4 + i] = make_uint2(l0, l1);
    }
}

// ===========================================================================
// MMA attention: block = (token t, kv head), 128 threads (4 warps).
// ===========================================================================
#define AK_H 0
#define AK_L 18432
#define AV_H 36864
#define AV_L 55296
#define AQ_H 73728
#define AQ_L 74880
#define AS_F 76032
#define AP_H 81152
#define AP_L 83328
#define AO_F 85504
#define ATTN_SMEM 87808

__global__ void __launch_bounds__(128) attn_kernel(
    const __nv_bfloat16* __restrict__ qh, const __nv_bfloat16* __restrict__ ql,
    const float* __restrict__ sinks,
    __nv_bfloat16* __restrict__ outh, __nv_bfloat16* __restrict__ outl)
{
    extern __shared__ char smc[];
    const uint32_t sb = smem_u32(smc);
    const int t   = blockIdx.x;
    const int hkv = blockIdx.y;
    const int j0  = max(0, t - (WIN - 1));
    const int cnt = t - j0 + 1;
    const int tid = threadIdx.x;
    const int warp = tid >> 5;
    const int lane = tid & 31;

    const size_t koff = QDIM + (size_t)hkv * HD;
    const size_t voff = QDIM + NKV * HD + (size_t)hkv * HD;
    for (int i = tid; i < WIN * 8; i += 128) {
        int j = i >> 3, c8 = i & 7;
        int jc = min(j, cnt - 1);
        uint32_t sz = (j < cnt) ? 16u : 0u;
        size_t rowk = (size_t)(j0 + jc) * QKV_DIM + koff + c8 * 8;
        size_t rowv = (size_t)(j0 + jc) * QKV_DIM + voff + c8 * 8;
        uint32_t off = (uint32_t)j * 144u + (uint32_t)c8 * 16u;
        cp16(sb + AK_H + off, qh + rowk, sz);
        cp16(sb + AK_L + off, ql + rowk, sz);
        cp16(sb + AV_H + off, qh + rowv, sz);
        cp16(sb + AV_L + off, ql + rowv, sz);
    }
    {
        int i = tid;
        int hilo = i >> 6, h = (i >> 3) & 7, c8 = i & 7;
        size_t src = (size_t)t * QKV_DIM + (hkv * 8 + h) * HD + c8 * 8;
        uint32_t off = (uint32_t)h * 144u + (uint32_t)c8 * 16u;
        if (hilo == 0) cp16(sb + AQ_H + off, qh + src, 16);
        else           cp16(sb + AQ_L + off, ql + src, 16);
    }
    cp_commit();
    cp_wait<0>();
    __syncthreads();

    // ---- QK: S^T[j][h] ----
    {
        uint32_t bh[4][2], bl[4][2];
        #pragma unroll
        for (int ks = 0; ks < 4; ks++) {
            uint32_t addr = sb + AQ_H + (uint32_t)(lane & 7) * 144u
                          + (uint32_t)ks * 32u + (uint32_t)((lane >> 3) & 1) * 16u;
            ldsm_x2(bh[ks], addr);
            ldsm_x2(bl[ks], addr + (AQ_L - AQ_H));
        }
        float* Sf = (float*)(smc + AS_F);
        #pragma unroll
        for (int mi = 0; mi < 2; mi++) {
            const int mt = warp * 2 + mi;
            float c[4] = {0.f, 0.f, 0.f, 0.f};
            #pragma unroll
            for (int ks = 0; ks < 4; ks++) {
                uint32_t ah[4], al[4];
                uint32_t addr = sb + AK_H
                              + (uint32_t)(mt * 16 + (lane & 15)) * 144u
                              + (uint32_t)ks * 32u + (uint32_t)(lane >> 4) * 16u;
                ldsm_x4(ah, addr);
                ldsm_x4(al, addr + (AK_L - AK_H));
                mma16816(c, ah, bh[ks]);
                mma16816(c, al, bh[ks]);
                mma16816(c, ah, bl[ks]);
            }
            int j  = mt * 16 + (lane >> 2);
            int hc = (lane & 3) * 2;
            *(float2*)&Sf[j * 10 + hc]       = make_float2(c[0], c[1]);
            *(float2*)&Sf[(j + 8) * 10 + hc] = make_float2(c[2], c[3]);
        }
    }
    __syncthreads();

    // ---- softmax per head ----
    {
        const float* Sf = (const float*)(smc + AS_F);
        __nv_bfloat16* Ph = (__nv_bfloat16*)(smc + AP_H);
        __nv_bfloat16* Pl = (__nv_bfloat16*)(smc + AP_L);
        #pragma unroll
        for (int hi = 0; hi < 2; hi++) {
            const int h = warp * 2 + hi;
            float s[4], m = -INFINITY;
            #pragma unroll
            for (int r = 0; r < 4; r++) {
                int j = lane + r * 32;
                s[r] = (j < cnt) ? Sf[j * 10 + h] : -INFINITY;
                m = fmaxf(m, s[r]);
            }
            #pragma unroll
            for (int o = 16; o; o >>= 1) m = fmaxf(m, __shfl_xor_sync(~0u, m, o));
            float sum = 0.f;
            #pragma unroll
            for (int r = 0; r < 4; r++) {
                float e = (s[r] == -INFINITY) ? 0.f : expf(s[r] - m);
                s[r] = e;
                sum += e;
            }
            #pragma unroll
            for (int o = 16; o; o >>= 1) sum += __shfl_xor_sync(~0u, sum, o);
            const float invd = 1.f / (sum + expf(sinks[hkv * 8 + h] - m));
            #pragma unroll
            for (int r = 0; r < 4; r++) {
                int j = lane + r * 32;
                float p = s[r] * invd;
                __nv_bfloat16 ph = __float2bfloat16(p);
                __nv_bfloat16 pl = __float2bfloat16(p - __bfloat162float(ph));
                Ph[h * 136 + j] = ph;
                Pl[h * 136 + j] = pl;
            }
        }
    }
    __syncthreads();

    // ---- PV: O^T[d][h] ----
    {
        float c[4] = {0.f, 0.f, 0.f, 0.f};
        #pragma unroll
        for (int kt = 0; kt < 8; kt++) {
            uint32_t ah[4], al[4], bh[2], bl[2];
            uint32_t jrow = (uint32_t)(kt * 16 + (lane & 7) + ((lane >> 4) & 1) * 8);
            uint32_t dcol = (uint32_t)(warp * 16 + ((lane >> 3) & 1) * 8);
            uint32_t va = sb + AV_H + jrow * 144u + dcol * 2u;
            ldsm_x4t(ah, va);
            ldsm_x4t(al, va + (AV_L - AV_H));
            uint32_t pa = sb + AP_H + (uint32_t)(lane & 7) * 272u
                        + (uint32_t)kt * 32u + (uint32_t)((lane >> 3) & 1) * 16u;
            ldsm_x2(bh, pa);
            ldsm_x2(bl, pa + (AP_L - AP_H));
            mma16816(c, ah, bh);
            mma16816(c, al, bh);
            mma16816(c, ah, bl);
        }
        float* Os = (float*)(smc + AO_F);
        int d  = warp * 16 + (lane >> 2);
        int hc = (lane & 3) * 2;
        Os[d * 9 + hc]           = c[0];
        Os[d * 9 + hc + 1]       = c[1];
        Os[(d + 8) * 9 + hc]     = c[2];
        Os[(d + 8) * 9 + hc + 1] = c[3];
    }
    __syncthreads();

    {
        const float* Os = (const float*)(smc + AO_F);
        int o = tid * 4;
        int h = o >> 6, d0 = o & 63;
        float f0 = Os[(d0 + 0) * 9 + h];
        float f1 = Os[(d0 + 1) * 9 + h];
        float f2 = Os[(d0 + 2) * 9 + h];
        float f3 = Os[(d0 + 3) * 9 + h];
        uint32_t h0, l0, h1, l1;
        split_pair(f0, f1, h0, l0);
        split_pair(f2, f3, h1, l1);
        size_t base = (size_t)t * QDIM + hkv * 512 + o;
        *(uint2*)(outh + base) = make_uint2(h0, h1);
        *(uint2*)(outl + base) = make_uint2(l0, l1);
    }
}

// ---------------------------------------------------------------------------
extern "C" void kernel_launch(void* const* d_in, const int* in_sizes, int n_in,
                              void* d_out, int out_size)
{
    const float* x      = (const float*)d_in[0];
    const float* W_qkv  = (const float*)d_in[1];
    const float* b_qkv  = (const float*)d_in[2];
    const float* W_out  = (const float*)d_in[3];
    const float* b_out  = (const float*)d_in[4];
    const float* sinks  = (const float*)d_in[5];
    float* out = (float*)d_out;

    float *qkv_ptr, *invf_ptr;
    __nv_bfloat16 *xh, *xl, *wqh, *wql, *woh, *wol, *ath, *atl, *qh, *ql;
    cudaGetSymbolAddress((void**)&qkv_ptr, g_qkv);
    cudaGetSymbolAddress((void**)&invf_ptr, g_invf);
    cudaGetSymbolAddress((void**)&xh, g_xh);
    cudaGetSymbolAddress((void**)&xl, g_xl);
    cudaGetSymbolAddress((void**)&wqh, g_wqh);
    cudaGetSymbolAddress((void**)&wql, g_wql);
    cudaGetSymbolAddress((void**)&woh, g_woh);
    cudaGetSymbolAddress((void**)&wol, g_wol);
    cudaGetSymbolAddress((void**)&ath, g_ath);
    cudaGetSymbolAddress((void**)&atl, g_atl);
    cudaGetSymbolAddress((void**)&qh, g_qh);
    cudaGetSymbolAddress((void**)&ql, g_ql);

    cudaFuncSetAttribute(hmma_gemm_bias,
                         cudaFuncAttributeMaxDynamicSharedMemorySize,
                         GEMM_SMEM_BYTES);
    cudaFuncSetAttribute(attn_kernel, cudaFuncAttributeMaxDynamicSharedMemorySize,
                         ATTN_SMEM);

    // 0) rope table + split inputs to bf16 hi/lo
    rope_table_kernel<<<1, 32>>>(invf_ptr);
    {
        int n4 = T_SEQ * D_MODEL / 4;
        split_kernel<<<(n4 + 255) / 256, 256>>>(
            (const float4*)x, (uint2*)xh, (uint2*)xl, n4);
        n4 = D_MODEL * QKV_DIM / 4;
        split_kernel<<<(n4 + 255) / 256, 256>>>(
            (const float4*)W_qkv, (uint2*)wqh, (uint2*)wql, n4);
        n4 = QDIM * D_MODEL / 4;
        split_kernel<<<(n4 + 255) / 256, 256>>>(
            (const float4*)W_out, (uint2*)woh, (uint2*)wol, n4);
    }

    // 1) qkv = x @ W_qkv + b_qkv          (1536 x 5120, K=2880)
    {
        dim3 grid(QKV_DIM / 128, T_SEQ / 128);
        hmma_gemm_bias<<<grid, 256, GEMM_SMEM_BYTES>>>(
            xh, xl, wqh, wql, b_qkv, qkv_ptr, T_SEQ, QKV_DIM, D_MODEL);
    }
    // 2) fused rope + scale + split -> g_qh / g_ql
    rope_split_qkv<<<T_SEQ, 256>>>(qkv_ptr, invf_ptr, qh, ql);

    // 3) sliding-window GQA attention with sinks -> split bf16
    {
        dim3 grid(T_SEQ, NKV);
        attn_kernel<<<grid, 128, ATTN_SMEM>>>(qh, ql, sinks, ath, atl);
    }
    // 4) out = attn @ W_out + b_out       (1536 x 2880, K=4096)
    {
        dim3 grid((D_MODEL + 127) / 128, T_SEQ / 128);
        hmma_gemm_bias<<<grid, 256, GEMM_SMEM_BYTES>>>(
            ath, atl, woh, wol, b_out, out, T_SEQ, D_MODEL, QDIM);
    }
}

// round 15
// speedup vs baseline: 5.1188x; 1.0716x over previous
#include <cuda_runtime.h>
#include <cuda_bf16.h>
#include <math.h>
#include <cstdint>

// Problem dims (fixed by reference)
#define T_SEQ   1536
#define D_MODEL 2880
#define NH      64
#define NKV     8
#define HD      64
#define QKV_DIM 5120          // 64*(64+16)
#define QDIM    4096          // NH*HD
#define WIN     128
#define SM_SCALE 0.125f

// Scratch (allocation-free rule: device globals)
__device__ float g_qkv[T_SEQ * QKV_DIM];            // fp32 qkv (GEMM1 out)
__device__ float g_invf[32];                        // rope inv_freq table
// split-bf16 operands
__device__ __nv_bfloat16 g_xh[T_SEQ * D_MODEL];
__device__ __nv_bfloat16 g_xl[T_SEQ * D_MODEL];
__device__ __nv_bfloat16 g_wqh[D_MODEL * QKV_DIM];
__device__ __nv_bfloat16 g_wql[D_MODEL * QKV_DIM];
__device__ __nv_bfloat16 g_woh[QDIM * D_MODEL];
__device__ __nv_bfloat16 g_wol[QDIM * D_MODEL];
__device__ __nv_bfloat16 g_ath[T_SEQ * QDIM];       // attn out hi
__device__ __nv_bfloat16 g_atl[T_SEQ * QDIM];       // attn out lo
__device__ __nv_bfloat16 g_qh[T_SEQ * QKV_DIM];     // roped/scaled qkv hi
__device__ __nv_bfloat16 g_ql[T_SEQ * QKV_DIM];     // roped/scaled qkv lo

// ===========================================================================
// PTX helpers
// ===========================================================================
__device__ __forceinline__ uint32_t smem_u32(const void* p) {
    uint32_t a;
    asm("{ .reg .u64 t; cvta.to.shared.u64 t, %1; cvt.u32.u64 %0, t; }"
        : "=r"(a) : "l"(p));
    return a;
}
__device__ __forceinline__ void ldsm_x4(uint32_t r[4], uint32_t a) {
    asm volatile("ldmatrix.sync.aligned.m8n8.x4.shared.b16 {%0,%1,%2,%3}, [%4];"
        : "=r"(r[0]), "=r"(r[1]), "=r"(r[2]), "=r"(r[3]) : "r"(a));
}
__device__ __forceinline__ void ldsm_x4t(uint32_t r[4], uint32_t a) {
    asm volatile("ldmatrix.sync.aligned.m8n8.x4.trans.shared.b16 {%0,%1,%2,%3}, [%4];"
        : "=r"(r[0]), "=r"(r[1]), "=r"(r[2]), "=r"(r[3]) : "r"(a));
}
__device__ __forceinline__ void ldsm_x2(uint32_t r[2], uint32_t a) {
    asm volatile("ldmatrix.sync.aligned.m8n8.x2.shared.b16 {%0,%1}, [%2];"
        : "=r"(r[0]), "=r"(r[1]) : "r"(a));
}
__device__ __forceinline__ void mma16816(float c[4], const uint32_t a[4],
                                         const uint32_t b[2]) {
    asm volatile(
        "mma.sync.aligned.m16n8k16.row.col.f32.bf16.bf16.f32 "
        "{%0,%1,%2,%3}, {%4,%5,%6,%7}, {%8,%9}, {%0,%1,%2,%3};"
        : "+f"(c[0]), "+f"(c[1]), "+f"(c[2]), "+f"(c[3])
        : "r"(a[0]), "r"(a[1]), "r"(a[2]), "r"(a[3]), "r"(b[0]), "r"(b[1]));
}
__device__ __forceinline__ void cp16(uint32_t saddr, const void* gaddr,
                                     uint32_t srcsize) {
    asm volatile("cp.async.ca.shared.global [%0], [%1], 16, %2;"
        :: "r"(saddr), "l"(gaddr), "r"(srcsize));
}
__device__ __forceinline__ void cp_commit() {
    asm volatile("cp.async.commit_group;" ::: "memory");
}
template <int N>
__device__ __forceinline__ void cp_wait() {
    asm volatile("cp.async.wait_group %0;" :: "n"(N) : "memory");
}
// split fp32 pair into (hi, lo) packed bf16x2
__device__ __forceinline__ void split_pair(float x, float y,
                                           uint32_t& hi, uint32_t& lo) {
    __nv_bfloat16 hx = __float2bfloat16(x);
    __nv_bfloat16 hy = __float2bfloat16(y);
    float rx = x - __bfloat162float(hx);
    float ry = y - __bfloat162float(hy);
    __nv_bfloat162 hp = __halves2bfloat162(hx, hy);
    __nv_bfloat162 lp = __floats2bfloat162_rn(rx, ry);
    hi = *reinterpret_cast<uint32_t*>(&hp);
    lo = *reinterpret_cast<uint32_t*>(&lp);
}

// ===========================================================================
// Split kernel: fp32 -> (hi, lo) bf16, vectorized.
// ===========================================================================
__global__ void __launch_bounds__(256) split_kernel(
    const float4* __restrict__ in, uint2* __restrict__ hi,
    uint2* __restrict__ lo, int n4)
{
    int i = blockIdx.x * 256 + threadIdx.x;
    if (i < n4) {
        float4 v = in[i];
        uint32_t h0, l0, h1, l1;
        split_pair(v.x, v.y, h0, l0);
        split_pair(v.z, v.w, h1, l1);
        hi[i] = make_uint2(h0, h1);
        lo[i] = make_uint2(l0, l1);
    }
}

// ===========================================================================
// Split-bf16 HMMA GEMM with bias (pre-split operands, cp.async pipeline)
// 2 CTAs/SM via launch_bounds; B frags via ldsm.x4.trans (2 n-tiles/op).
// ===========================================================================
#define SA_HI_OFF 0
#define SA_LO_OFF 10240
#define SB_HI_OFF 20480
#define SB_LO_OFF 29184
#define BUF_STRIDE 37888
#define EP_PITCH  132
#define GEMM_SMEM_BYTES (2 * BUF_STRIDE)   // 75776 (epilogue 67584 aliases)

__global__ void __launch_bounds__(256, 2) hmma_gemm_bias(
    const __nv_bfloat16* __restrict__ Ah, const __nv_bfloat16* __restrict__ Al,
    const __nv_bfloat16* __restrict__ Bh, const __nv_bfloat16* __restrict__ Bl,
    const float* __restrict__ bias, float* __restrict__ C,
    int M, int N, int K)
{
    extern __shared__ char smem[];
    const uint32_t sb = smem_u32(smem);
    const int tid = threadIdx.x, lane = tid & 31, wid = tid >> 5;
    const int wm = wid >> 2, wn = wid & 3;
    const int m0 = blockIdx.y * 128, n0 = blockIdx.x * 128;

    float acc[4][4][4];
    #pragma unroll
    for (int mi = 0; mi < 4; mi++)
        #pragma unroll
        for (int ni = 0; ni < 4; ni++)
            #pragma unroll
            for (int q = 0; q < 4; q++) acc[mi][ni][q] = 0.f;

    const int am  = tid >> 2;
    const int aks = (tid & 3);
    const int bk  = tid >> 4;
    const int bns = (tid & 15);

    auto issue_chunk = [&](int k0, int buf) {
        const uint32_t bb = sb + (uint32_t)buf * BUF_STRIDE;
        #pragma unroll
        for (int r = 0; r < 2; r++) {
            int m = am + r * 64;
            const __nv_bfloat16* ga = Ah + (size_t)(m0 + m) * K + k0 + aks * 8;
            const __nv_bfloat16* gl = Al + (size_t)(m0 + m) * K + k0 + aks * 8;
            uint32_t so = (uint32_t)m * 80u + (uint32_t)aks * 16u;
            cp16(bb + SA_HI_OFF + so, ga, 16);
            cp16(bb + SA_LO_OFF + so, gl, 16);
        }
        #pragma unroll
        for (int r = 0; r < 2; r++) {
            int k = bk + r * 16;
            int ncol = n0 + bns * 8;
            uint32_t sz = (ncol < N) ? 16u : 0u;
            const __nv_bfloat16* gb = Bh + (size_t)(k0 + k) * N + ncol;
            const __nv_bfloat16* gl = Bl + (size_t)(k0 + k) * N + ncol;
            uint32_t so = (uint32_t)k * 272u + (uint32_t)bns * 16u;
            cp16(bb + SB_HI_OFF + so, gb, sz);
            cp16(bb + SB_LO_OFF + so, gl, sz);
        }
        cp_commit();
    };

    const int nch = K >> 5;
    issue_chunk(0, 0);

    for (int ch = 0; ch < nch; ch++) {
        if (ch + 1 < nch) {
            issue_chunk((ch + 1) * 32, (ch + 1) & 1);
            cp_wait<1>();
        } else {
            cp_wait<0>();
        }
        __syncthreads();

        const uint32_t bufb = sb + (uint32_t)(ch & 1) * BUF_STRIDE;
        #pragma unroll
        for (int s = 0; s < 2; s++) {
            uint32_t ah[4][4], al[4][4], bh[4][2], bl[4][2];
            const uint32_t arow  = (uint32_t)(lane & 15);
            const uint32_t acolb = (uint32_t)(s * 32 + (lane >> 4) * 16);
            #pragma unroll
            for (int mi = 0; mi < 4; mi++) {
                uint32_t addr = bufb + SA_HI_OFF
                              + (uint32_t)(wm * 64 + mi * 16 + arow) * 80u + acolb;
                ldsm_x4(ah[mi], addr);
                ldsm_x4(al[mi], addr + (SA_LO_OFF - SA_HI_OFF));
            }
            const uint32_t brow = (uint32_t)(s * 16 + (lane & 15));
            #pragma unroll
            for (int pr = 0; pr < 2; pr++) {
                uint32_t bt[4], btl[4];
                uint32_t addr = bufb + SB_HI_OFF + brow * 272u
                              + (uint32_t)(wn * 32 + pr * 16
                                           + ((lane >> 4) & 1) * 8) * 2u;
                ldsm_x4t(bt, addr);
                ldsm_x4t(btl, addr + (SB_LO_OFF - SB_HI_OFF));
                bh[pr * 2][0]     = bt[0];  bh[pr * 2][1]     = bt[1];
                bh[pr * 2 + 1][0] = bt[2];  bh[pr * 2 + 1][1] = bt[3];
                bl[pr * 2][0]     = btl[0]; bl[pr * 2][1]     = btl[1];
                bl[pr * 2 + 1][0] = btl[2]; bl[pr * 2 + 1][1] = btl[3];
            }
            #pragma unroll
            for (int mi = 0; mi < 4; mi++)
                #pragma unroll
                for (int ni = 0; ni < 4; ni++) {
                    mma16816(acc[mi][ni], ah[mi], bh[ni]);
                    mma16816(acc[mi][ni], al[mi], bh[ni]);
                    mma16816(acc[mi][ni], ah[mi], bl[ni]);
                }
        }
        __syncthreads();
    }

    float* ep = (float*)smem;
    #pragma unroll
    for (int mi = 0; mi < 4; mi++) {
        int r0 = wm * 64 + mi * 16 + (lane >> 2);
        #pragma unroll
        for (int ni = 0; ni < 4; ni++) {
            int c = wn * 32 + ni * 8 + (lane & 3) * 2;
            ep[r0 * EP_PITCH + c]           = acc[mi][ni][0];
            ep[r0 * EP_PITCH + c + 1]       = acc[mi][ni][1];
            ep[(r0 + 8) * EP_PITCH + c]     = acc[mi][ni][2];
            ep[(r0 + 8) * EP_PITCH + c + 1] = acc[mi][ni][3];
        }
    }
    __syncthreads();
    for (int i = tid; i < 4096; i += 256) {
        int r = i >> 5, cq = (i & 31) * 4;
        int col = n0 + cq;
        if (col < N) {
            float4 b4 = *(const float4*)(bias + col);
            float4 o;
            o.x = ep[r * EP_PITCH + cq + 0] + b4.x;
            o.y = ep[r * EP_PITCH + cq + 1] + b4.y;
            o.z = ep[r * EP_PITCH + cq + 2] + b4.z;
            o.w = ep[r * EP_PITCH + cq + 3] + b4.w;
            *(float4*)(C + (size_t)(m0 + r) * N + col) = o;
        }
    }
}

// ---------------------------------------------------------------------------
// RoPE inv_freq table init (32 threads, double precision, once per launch)
// ---------------------------------------------------------------------------
__global__ void rope_table_kernel(float* __restrict__ invf_out)
{
    const int i = threadIdx.x;   // 0..31
    const double lgbase = log(150000.0);
    const double low  = 32.0 * log(1024.0 / (32.0 * 2.0 * M_PI)) / lgbase;
    const double high = 32.0 * log(1024.0 / ( 1.0 * 2.0 * M_PI)) / lgbase;
    double freq = pow(150000.0, (double)(2 * i) / 64.0);
    double ramp = ((double)i - low) / (high - low);
    ramp = fmin(1.0, fmax(0.0, ramp));
    double invf = ramp / (32.0 * freq) + (1.0 - ramp) / freq;
    invf_out[i] = (float)invf;
}

// ===========================================================================
// Fused RoPE + scale + split (one block per token, 256 threads)
// ===========================================================================
__global__ void __launch_bounds__(256) rope_split_qkv(
    const float* __restrict__ qkv, const float* __restrict__ invf,
    __nv_bfloat16* __restrict__ qh, __nv_bfloat16* __restrict__ ql)
{
    __shared__ float sinv[32];
    const int t = blockIdx.x;
    const int tid = threadIdx.x;
    if (tid < 32) sinv[tid] = invf[tid];
    __syncthreads();

    const float conc = 0.1f * logf(32.0f) + 1.0f;
    const float* row = qkv + (size_t)t * QKV_DIM;
    uint2* oh = (uint2*)(qh + (size_t)t * QKV_DIM);
    uint2* ol = (uint2*)(ql + (size_t)t * QKV_DIM);

    for (int i = tid; i < (NH + NKV) * 8; i += 256) {
        int hh = i >> 3, c = i & 7;
        int base = (hh < NH) ? hh * HD : QDIM + (hh - NH) * HD;
        const float4 a = ((const float4*)(row + base))[c];
        const float4 b = ((const float4*)(row + base))[c + 8];
        float na[4], nb[4];
        const float av[4] = {a.x, a.y, a.z, a.w};
        const float bv[4] = {b.x, b.y, b.z, b.w};
        #pragma unroll
        for (int q = 0; q < 4; q++) {
            float ang = (float)t * sinv[c * 4 + q];
            float s, cc;
            sincosf(ang, &s, &cc);
            cc *= conc; s *= conc;
            na[q] = av[q] * cc - bv[q] * s;
            nb[q] = bv[q] * cc + av[q] * s;
        }
        if (hh < NH) {
            #pragma unroll
            for (int q = 0; q < 4; q++) { na[q] *= SM_SCALE; nb[q] *= SM_SCALE; }
        }
        uint32_t h0, l0, h1, l1;
        split_pair(na[0], na[1], h0, l0);
        split_pair(na[2], na[3], h1, l1);
        oh[base / 4 + c] = make_uint2(h0, h1);
        ol[base / 4 + c] = make_uint2(l0, l1);
        split_pair(nb[0], nb[1], h0, l0);
        split_pair(nb[2], nb[3], h1, l1);
        oh[base / 4 + c + 8] = make_uint2(h0, h1);
        ol[base / 4 + c + 8] = make_uint2(l0, l1);
    }
    const int vbase4 = (QDIM + NKV * HD) / 4;
    for (int i = tid; i < 128; i += 256) {
        float4 v = ((const float4*)row)[vbase4 + i];
        uint32_t h0, l0, h1, l1;
        split_pair(v.x, v.y, h0, l0);
        split_pair(v.z, v.w, h1, l1);
        oh[vbase4 + i] = make_uint2(h0, h1);
        ol[vbase4 + i] = make_uint2(l0, l1);
    }
}

// ===========================================================================
// 8-token tiled MMA attention: block = (8 tokens, kv head), 256 threads.
//   Window union = 135 rows -> 9 j-tiles of 16 (144).
//   QK: warp w owns token w (8 heads = 1 n-tile); S in registers;
//       warp-local softmax (mask uniform per warp); P -> smem split bf16.
//   PV: warp w = (d-tile w&3, token-quad w>>2); V^T via ldsm.x4.trans.
// ===========================================================================
#define TQ   8
#define JT   144
#define BK_H 0
#define BK_L 20736
#define BV_H 41472
#define BV_L 62208
#define BQ_H 82944
#define BQ_L 92160
#define BP_H 101376
#define BP_L 120832
#define BO_F BQ_H                    // fp32 [64 q][68 d] aliases Q (17408<=18432)
#define ATTN_SMEM 140288

__global__ void __launch_bounds__(256) attn_kernel(
    const __nv_bfloat16* __restrict__ qh, const __nv_bfloat16* __restrict__ ql,
    const float* __restrict__ sinks,
    __nv_bfloat16* __restrict__ outh, __nv_bfloat16* __restrict__ outl)
{
    extern __shared__ char smc[];
    const uint32_t sb = smem_u32(smc);
    const int t0  = blockIdx.x * TQ;
    const int hkv = blockIdx.y;
    const int j0  = max(0, t0 - (WIN - 1));
    const int cntrows = t0 + TQ - j0;          // <= 135
    const int tid = threadIdx.x;
    const int warp = tid >> 5;
    const int lane = tid & 31;

    // ---- fill K/V (144 rows x 8 16B-chunks each, 4 arrays) ----
    for (int i = tid; i < JT * 8; i += 256) {
        int jj = i >> 3, c8 = i & 7;
        int jc = min(jj, cntrows - 1);
        uint32_t sz = (jj < cntrows) ? 16u : 0u;
        size_t srck = (size_t)(j0 + jc) * QKV_DIM + QDIM + hkv * HD + c8 * 8;
        size_t srcv = srck + NKV * HD;
        uint32_t off = (uint32_t)jj * 144u + (uint32_t)c8 * 16u;
        cp16(sb + BK_H + off, qh + srck, sz);
        cp16(sb + BK_L + off, ql + srck, sz);
        cp16(sb + BV_H + off, qh + srcv, sz);
        cp16(sb + BV_L + off, ql + srcv, sz);
    }
    // ---- fill Q: 64 rows (tok*8+head) x 8 chunks x {hi,lo} ----
    for (int i = tid; i < 1024; i += 256) {
        int hilo = i >> 9, row = (i >> 3) & 63, c8 = i & 7;
        int tt = t0 + (row >> 3), head = row & 7;
        size_t src = (size_t)tt * QKV_DIM + (hkv * 8 + head) * HD + c8 * 8;
        uint32_t off = (uint32_t)row * 144u + (uint32_t)c8 * 16u;
        if (hilo == 0) cp16(sb + BQ_H + off, qh + src, 16);
        else           cp16(sb + BQ_L + off, ql + src, 16);
    }
    cp_commit();
    cp_wait<0>();
    __syncthreads();

    const int tw  = t0 + warp;                 // this warp's token
    const int jlo = max(0, tw - (WIN - 1) - j0);
    const int jhi = tw - j0;

    // ---- QK: S^T[jj][head] for token tw, 9 m-tiles in registers ----
    float sc[9][4];
    {
        uint32_t bh[4][2], bl[4][2];
        #pragma unroll
        for (int ks = 0; ks < 4; ks++) {
            uint32_t addr = sb + BQ_H
                          + (uint32_t)(warp * 8 + (lane & 7)) * 144u
                          + (uint32_t)ks * 32u + (uint32_t)((lane >> 3) & 1) * 16u;
            ldsm_x2(bh[ks], addr);
            ldsm_x2(bl[ks], addr + (BQ_L - BQ_H));
        }
        #pragma unroll
        for (int mt = 0; mt < 9; mt++) {
            float c[4] = {0.f, 0.f, 0.f, 0.f};
            #pragma unroll
            for (int ks = 0; ks < 4; ks++) {
                uint32_t ah[4], al[4];
                uint32_t addr = sb + BK_H
                              + (uint32_t)(mt * 16 + (lane & 15)) * 144u
                              + (uint32_t)ks * 32u + (uint32_t)(lane >> 4) * 16u;
                ldsm_x4(ah, addr);
                ldsm_x4(al, addr + (BK_L - BK_H));
                mma16816(c, ah, bh[ks]);
                mma16816(c, al, bh[ks]);
                mma16816(c, ah, bl[ks]);
            }
            sc[mt][0] = c[0]; sc[mt][1] = c[1]; sc[mt][2] = c[2]; sc[mt][3] = c[3];
        }
    }

    // ---- warp-local softmax (mask uniform for this warp's token) ----
    {
        const int jb = lane >> 2;
        float m0 = -INFINITY, m1 = -INFINITY;
        #pragma unroll
        for (int mt = 0; mt < 9; mt++) {
            #pragma unroll
            for (int k = 0; k < 4; k++) {
                int jj = mt * 16 + jb + (k >> 1) * 8;
                if (jj < jlo || jj > jhi) sc[mt][k] = -INFINITY;
                if (k & 1) m1 = fmaxf(m1, sc[mt][k]);
                else       m0 = fmaxf(m0, sc[mt][k]);
            }
        }
        #pragma unroll
        for (int o = 4; o <= 16; o <<= 1) {
            m0 = fmaxf(m0, __shfl_xor_sync(~0u, m0, o));
            m1 = fmaxf(m1, __shfl_xor_sync(~0u, m1, o));
        }
        float s0 = 0.f, s1 = 0.f;
        #pragma unroll
        for (int mt = 0; mt < 9; mt++) {
            #pragma unroll
            for (int k = 0; k < 4; k++) {
                float m = (k & 1) ? m1 : m0;
                float e = (sc[mt][k] == -INFINITY) ? 0.f : expf(sc[mt][k] - m);
                sc[mt][k] = e;
                if (k & 1) s1 += e; else s0 += e;
            }
        }
        #pragma unroll
        for (int o = 4; o <= 16; o <<= 1) {
            s0 += __shfl_xor_sync(~0u, s0, o);
            s1 += __shfl_xor_sync(~0u, s1, o);
        }
        const int h0 = 2 * (lane & 3), h1 = h0 + 1;
        const float i0 = 1.f / (s0 + expf(sinks[hkv * 8 + h0] - m0));
        const float i1 = 1.f / (s1 + expf(sinks[hkv * 8 + h1] - m1));
        __nv_bfloat16* Ph = (__nv_bfloat16*)(smc + BP_H);
        __nv_bfloat16* Pl = (__nv_bfloat16*)(smc + BP_L);
        const int q0 = warp * 8 + h0;
        #pragma unroll
        for (int mt = 0; mt < 9; mt++) {
            #pragma unroll
            for (int k = 0; k < 4; k++) {
                int jj = mt * 16 + jb + (k >> 1) * 8;
                float p = sc[mt][k] * ((k & 1) ? i1 : i0);
                __nv_bfloat16 ph = __float2bfloat16(p);
                __nv_bfloat16 pl = __float2bfloat16(p - __bfloat162float(ph));
                int q = q0 + (k & 1);
                Ph[q * 152 + jj] = ph;
                Pl[q * 152 + jj] = pl;
            }
        }
    }
    __syncthreads();

    // ---- PV: warp = (d-tile dt, token-quad th): O^T[d][q] ----
    {
        const int dt = warp & 3, th = warp >> 2;
        float oc[4][4];
        #pragma unroll
        for (int tt = 0; tt < 4; tt++)
            #pragma unroll
            for (int k = 0; k < 4; k++) oc[tt][k] = 0.f;

        #pragma unroll
        for (int kt = 0; kt < 9; kt++) {
            uint32_t ah[4], al[4];
            uint32_t jrow = (uint32_t)(kt * 16 + (lane & 7) + ((lane >> 4) & 1) * 8);
            uint32_t dcol = (uint32_t)(dt * 16 + ((lane >> 3) & 1) * 8);
            uint32_t va = sb + BV_H + jrow * 144u + dcol * 2u;
            ldsm_x4t(ah, va);
            ldsm_x4t(al, va + (BV_L - BV_H));
            #pragma unroll
            for (int tt = 0; tt < 4; tt++) {
                uint32_t bh[2], bl[2];
                uint32_t pa = sb + BP_H
                            + (uint32_t)((th * 4 + tt) * 8 + (lane & 7)) * 304u
                            + (uint32_t)kt * 32u + (uint32_t)((lane >> 3) & 1) * 16u;
                ldsm_x2(bh, pa);
                ldsm_x2(bl, pa + (BP_L - BP_H));
                mma16816(oc[tt], ah, bh);
                mma16816(oc[tt], al, bh);
                mma16816(oc[tt], ah, bl);
            }
        }
        __syncthreads();   // Q reads long done; safe to alias BO_F over Q region
        float* Os = (float*)(smc + BO_F);
        #pragma unroll
        for (int tt = 0; tt < 4; tt++) {
            int q = (th * 4 + tt) * 8 + 2 * (lane & 3);
            int d = dt * 16 + (lane >> 2);
            Os[q * 68 + d]           = oc[tt][0];
            Os[(q + 1) * 68 + d]     = oc[tt][1];
            Os[q * 68 + d + 8]       = oc[tt][2];
            Os[(q + 1) * 68 + d + 8] = oc[tt][3];
        }
    }
    __syncthreads();

    // ---- write output: split bf16, coalesced ----
    {
        const float* Os = (const float*)(smc + BO_F);
        int q = tid >> 2, d0 = (tid & 3) * 16;
        int tt = t0 + (q >> 3), h = q & 7;
        size_t base = (size_t)tt * QDIM + hkv * 512 + h * HD + d0;
        #pragma unroll
        for (int e = 0; e < 16; e += 4) {
            float f0 = Os[q * 68 + d0 + e];
            float f1 = Os[q * 68 + d0 + e + 1];
            float f2 = Os[q * 68 + d0 + e + 2];
            float f3 = Os[q * 68 + d0 + e + 3];
            uint32_t h0, l0, h1, l1;
            split_pair(f0, f1, h0, l0);
            split_pair(f2, f3, h1, l1);
            *(uint2*)(outh + base + e) = make_uint2(h0, h1);
            *(uint2*)(outl + base + e) = make_uint2(l0, l1);
        }
    }
}

// ---------------------------------------------------------------------------
extern "C" void kernel_launch(void* const* d_in, const int* in_sizes, int n_in,
                              void* d_out, int out_size)
{
    const float* x      = (const float*)d_in[0];
    const float* W_qkv  = (const float*)d_in[1];
    const float* b_qkv  = (const float*)d_in[2];
    const float* W_out  = (const float*)d_in[3];
    const float* b_out  = (const float*)d_in[4];
    const float* sinks  = (const float*)d_in[5];
    float* out = (float*)d_out;

    float *qkv_ptr, *invf_ptr;
    __nv_bfloat16 *xh, *xl, *wqh, *wql, *woh, *wol, *ath, *atl, *qh, *ql;
    cudaGetSymbolAddress((void**)&qkv_ptr, g_qkv);
    cudaGetSymbolAddress((void**)&invf_ptr, g_invf);
    cudaGetSymbolAddress((void**)&xh, g_xh);
    cudaGetSymbolAddress((void**)&xl, g_xl);
    cudaGetSymbolAddress((void**)&wqh, g_wqh);
    cudaGetSymbolAddress((void**)&wql, g_wql);
    cudaGetSymbolAddress((void**)&woh, g_woh);
    cudaGetSymbolAddress((void**)&wol, g_wol);
    cudaGetSymbolAddress((void**)&ath, g_ath);
    cudaGetSymbolAddress((void**)&atl, g_atl);
    cudaGetSymbolAddress((void**)&qh, g_qh);
    cudaGetSymbolAddress((void**)&ql, g_ql);

    cudaFuncSetAttribute(hmma_gemm_bias,
                         cudaFuncAttributeMaxDynamicSharedMemorySize,
                         GEMM_SMEM_BYTES);
    cudaFuncSetAttribute(attn_kernel, cudaFuncAttributeMaxDynamicSharedMemorySize,
                         ATTN_SMEM);

    // 0) rope table + split inputs to bf16 hi/lo
    rope_table_kernel<<<1, 32>>>(invf_ptr);
    {
        int n4 = T_SEQ * D_MODEL / 4;
        split_kernel<<<(n4 + 255) / 256, 256>>>(
            (const float4*)x, (uint2*)xh, (uint2*)xl, n4);
        n4 = D_MODEL * QKV_DIM / 4;
        split_kernel<<<(n4 + 255) / 256, 256>>>(
            (const float4*)W_qkv, (uint2*)wqh, (uint2*)wql, n4);
        n4 = QDIM * D_MODEL / 4;
        split_kernel<<<(n4 + 255) / 256, 256>>>(
            (const float4*)W_out, (uint2*)woh, (uint2*)wol, n4);
    }

    // 1) qkv = x @ W_qkv + b_qkv          (1536 x 5120, K=2880)
    {
        dim3 grid(QKV_DIM / 128, T_SEQ / 128);
        hmma_gemm_bias<<<grid, 256, GEMM_SMEM_BYTES>>>(
            xh, xl, wqh, wql, b_qkv, qkv_ptr, T_SEQ, QKV_DIM, D_MODEL);
    }
    // 2) fused rope + scale + split -> g_qh / g_ql
    rope_split_qkv<<<T_SEQ, 256>>>(qkv_ptr, invf_ptr, qh, ql);

    // 3) 8-token tiled sliding-window GQA attention with sinks
    {
        dim3 grid(T_SEQ / TQ, NKV);
        attn_kernel<<<grid, 256, ATTN_SMEM>>>(qh, ql, sinks, ath, atl);
    }
    // 4) out = attn @ W_out + b_out       (1536 x 2880, K=4096)
    {
        dim3 grid((D_MODEL + 127) / 128, T_SEQ / 128);
        hmma_gemm_bias<<<grid, 256, GEMM_SMEM_BYTES>>>(
            ath, atl, woh, wol, b_out, out, T_SEQ, D_MODEL, QDIM);
    }
}